// round 14
// baseline (speedup 1.0000x reference)
#include <cuda_runtime.h>
#include <cuda_fp16.h>
#include <mma.h>
#include <math.h>
#include <cstdint>

using namespace nvcuda;

// Problem constants
#define BB 2
#define LL 2048
#define DD 1024
#define NQH 8
#define NKVH 2
#define HD 128
#define FFND 4096
#define ROWS (BB*LL)            // 4096
#define EPSV 1.1920929e-07f

// ---------------- scratch (device globals; no allocs allowed) ----------------
__device__ half  g_h  [ROWS*DD];        // rmsnorm1 out (fp16)
__device__ half  g_q  [ROWS*NQH*HD];    // q proj (fp16, roped in epilogue)
__device__ half  g_k  [ROWS*NKVH*HD];   // k proj (fp16, roped in epilogue)
__device__ half  g_v  [ROWS*NKVH*HD];   // v proj (fp16)
__device__ half  g_ctx[ROWS*DD];        // attention out (fp16)
__device__ float g_x1 [ROWS*DD];        // post-attn residual (fp32)
__device__ half  g_h2 [ROWS*DD];        // rmsnorm2 out (fp16)
__device__ half  g_act[ROWS*FFND];      // silu(g)*u (fp16)
// fp16 weight copies
__device__ half  g_wqh[DD*NQH*HD];
__device__ half  g_wkh[DD*NKVH*HD];
__device__ half  g_wvh[DD*NKVH*HD];
__device__ half  g_woh[DD*DD];
__device__ half  g_wgh[DD*FFND];
__device__ half  g_wuh[DD*FFND];
__device__ half  g_wdh[FFND*DD];
// rope tables (fp32)
__device__ float g_rsin[LL*64];
__device__ float g_rcos[LL*64];

// ---------------- pack helpers ----------------
union HPack { half2 h[2]; uint2 u; };
__device__ __forceinline__ uint2 pack4(float a, float b, float c, float d) {
    HPack p;
    p.h[0] = __floats2half2_rn(a, b);
    p.h[1] = __floats2half2_rn(c, d);
    return p.u;
}
union HPack8 { half2 h[4]; uint4 u; };

// ---------------- fused weight conversion + rope table (one launch) ----------------
#define N4_WQ 262144
#define N4_WK 65536
#define N4_WV 65536
#define N4_WO 262144
#define N4_WG 1048576
#define N4_WU 1048576
#define N4_WD 1048576
#define N4_TOT (N4_WQ+N4_WK+N4_WV+N4_WO+N4_WG+N4_WU+N4_WD)   // 3801088
#define NROPE (LL*64)                                         // 131072
#define NCONV (N4_TOT + NROPE)

__global__ void convert_weights_kernel(
    const float* __restrict__ wq, const float* __restrict__ wk, const float* __restrict__ wv,
    const float* __restrict__ wo, const float* __restrict__ wg, const float* __restrict__ wu,
    const float* __restrict__ wd,
    half* __restrict__ wqh, half* __restrict__ wkh, half* __restrict__ wvh,
    half* __restrict__ woh, half* __restrict__ wgh, half* __restrict__ wuh,
    half* __restrict__ wdh, float* __restrict__ rsin, float* __restrict__ rcos)
{
    int i = blockIdx.x * blockDim.x + threadIdx.x;
    if (i >= NCONV) return;
    if (i >= N4_TOT) {
        int j = i - N4_TOT;
        int pos = j >> 6, d = j & 63;
        float freq = powf(10000.0f, (float)d * (2.0f / HD));
        float rad = (float)pos / freq;
        float sn, cs;
        sincosf(rad, &sn, &cs);
        rsin[j] = sn;
        rcos[j] = cs;
        return;
    }
    const float* src; half* dst; int off = i;
    if      (off < N4_WQ)                         { src = wq; dst = wqh; }
    else if ((off -= N4_WQ) < N4_WK)              { src = wk; dst = wkh; }
    else if ((off -= N4_WK) < N4_WV)              { src = wv; dst = wvh; }
    else if ((off -= N4_WV) < N4_WO)              { src = wo; dst = woh; }
    else if ((off -= N4_WO) < N4_WG)              { src = wg; dst = wgh; }
    else if ((off -= N4_WG) < N4_WU)              { src = wu; dst = wuh; }
    else    { off -= N4_WU;                         src = wd; dst = wdh; }
    float4 v = ((const float4*)src)[off];
    ((uint2*)dst)[off] = pack4(v.x, v.y, v.z, v.w);
}

// ---------------- RMSNorm (fp32 in, fp16 out) ----------------
__global__ __launch_bounds__(256) void rmsnorm_kernel(
    const float* __restrict__ x, const float* __restrict__ w, half* __restrict__ out)
{
    int row = blockIdx.x;
    const float4* xr = (const float4*)(x + (size_t)row * DD);
    float4 v = xr[threadIdx.x];
    float s = v.x*v.x + v.y*v.y + v.z*v.z + v.w*v.w;
    #pragma unroll
    for (int off = 16; off; off >>= 1) s += __shfl_xor_sync(0xffffffffu, s, off);
    __shared__ float red[8];
    if ((threadIdx.x & 31) == 0) red[threadIdx.x >> 5] = s;
    __syncthreads();
    float tot = red[0]+red[1]+red[2]+red[3]+red[4]+red[5]+red[6]+red[7];
    float r = rsqrtf(tot * (1.0f/DD) + EPSV);
    const float4 wv = ((const float4*)w)[threadIdx.x];
    ((uint2*)(out + (size_t)row * DD))[threadIdx.x] =
        pack4(v.x*r*wv.x, v.y*r*wv.y, v.z*r*wv.z, v.w*r*wv.w);
}

// ---------------- fp16 tensor-core GEMM core ----------------
#define APH 72
#define BPH 136
#define HASZ (128*APH)
#define HBSZ (64*BPH)
#define HSTG (HASZ + HBSZ)
#define GEMM_SMEM (2*HSTG*2)    // 71680 bytes

__device__ __forceinline__ void cp_async16h(half* smem, const half* g)
{
    unsigned int s = (unsigned int)__cvta_generic_to_shared(smem);
    asm volatile("cp.async.cg.shared.global [%0], [%1], 16;\n" :: "r"(s), "l"(g));
}

__device__ __forceinline__ void gemm_stage_load(
    half* As, half* Bs, const half* A, const half* B,
    int K, int ldb, int bm0, int col0, int k0, int tid)
{
    #pragma unroll
    for (int p = 0; p < 8; p++) {
        int idx = p * 128 + tid;
        int row = idx >> 3, c8 = (idx & 7) * 8;
        cp_async16h(As + row*APH + c8, A + (size_t)(bm0 + row)*K + k0 + c8);
    }
    #pragma unroll
    for (int p = 0; p < 8; p++) {
        int idx = p * 128 + tid;
        int br = idx >> 4, bc8 = (idx & 15) * 8;
        cp_async16h(Bs + br*BPH + bc8, B + (size_t)(k0 + br)*ldb + col0 + bc8);
    }
    asm volatile("cp.async.commit_group;\n" ::);
}

template <typename OT>
__device__ __forceinline__ void gemm_core(
    const half* __restrict__ A, const half* __restrict__ B,
    const float* __restrict__ Res, OT* __restrict__ C,
    int K, int ldb, int ldc, int bm0, int col0,
    const float* __restrict__ rsin, const float* __restrict__ rcos)
{
    extern __shared__ half smh[];
    int tid  = threadIdx.x;
    int warp = tid >> 5;
    int wm = warp & 1;
    int wn = warp >> 1;

    wmma::fragment<wmma::accumulator, 16,16,16, float> acc[4][4];
    #pragma unroll
    for (int i = 0; i < 4; i++)
        #pragma unroll
        for (int j = 0; j < 4; j++)
            wmma::fill_fragment(acc[i][j], 0.0f);

    int nk = K >> 6;

    gemm_stage_load(smh, smh + HASZ, A, B, K, ldb, bm0, col0, 0, tid);

    for (int kt = 0; kt < nk; kt++) {
        asm volatile("cp.async.wait_group 0;\n" ::);
        __syncthreads();

        if (kt + 1 < nk) {
            int s = (kt + 1) & 1;
            gemm_stage_load(smh + s*HSTG, smh + s*HSTG + HASZ, A, B, K, ldb, bm0, col0, (kt + 1) << 6, tid);
        }

        half* As = smh + (kt & 1) * HSTG;
        half* Bs = As + HASZ;
        #pragma unroll
        for (int ks = 0; ks < 4; ks++) {
            wmma::fragment<wmma::matrix_a, 16,16,16, half, wmma::row_major> af[4];
            wmma::fragment<wmma::matrix_b, 16,16,16, half, wmma::row_major> bf[4];
            #pragma unroll
            for (int i = 0; i < 4; i++)
                wmma::load_matrix_sync(af[i], As + (wm*64 + i*16)*APH + ks*16, APH);
            #pragma unroll
            for (int j = 0; j < 4; j++)
                wmma::load_matrix_sync(bf[j], Bs + (ks*16)*BPH + wn*64 + j*16, BPH);
            #pragma unroll
            for (int i = 0; i < 4; i++)
                #pragma unroll
                for (int j = 0; j < 4; j++)
                    wmma::mma_sync(acc[i][j], af[i], bf[j], acc[i][j]);
        }
    }

    if constexpr (sizeof(OT) == 4) {
        #pragma unroll
        for (int i = 0; i < 4; i++) {
            int r0 = bm0 + wm*64 + i*16;
            #pragma unroll
            for (int j = 0; j < 4; j++) {
                int c0 = col0 + wn*64 + j*16;
                if (Res) {
                    wmma::fragment<wmma::accumulator, 16,16,16, float> rf;
                    wmma::load_matrix_sync(rf, Res + (size_t)r0*ldc + c0, ldc, wmma::mem_row_major);
                    #pragma unroll
                    for (int e = 0; e < rf.num_elements; e++)
                        acc[i][j].x[e] += rf.x[e];
                }
                wmma::store_matrix_sync((float*)C + (size_t)r0*ldc + c0, acc[i][j], ldc, wmma::mem_row_major);
            }
        }
    } else {
        __syncthreads();
        float* scratch = (float*)smh;
        #pragma unroll
        for (int i = 0; i < 4; i++)
            #pragma unroll
            for (int j = 0; j < 4; j++)
                wmma::store_matrix_sync(scratch + warp*4096 + (i*16)*64 + j*16,
                                        acc[i][j], 64, wmma::mem_row_major);
        __syncthreads();
        #pragma unroll
        for (int it = 0; it < 16; it++) {
            int idx = it * 128 + tid;
            int row = idx >> 4, c8 = (idx & 15) * 8;
            int wid  = (row >> 6) + ((c8 >> 6) << 1);
            const float* src = scratch + wid*4096 + (row & 63)*64 + (c8 & 63);
            HPack8 p;
            if (rsin) {
                int cpart = c8 ^ 64;
                int widp = (row >> 6) + ((cpart >> 6) << 1);
                const float* par = scratch + widp*4096 + (row & 63)*64 + (c8 & 63);
                int pos = (bm0 + row) & (LL - 1);
                int d = c8 & 63;
                const float* sp = rsin + pos*64 + d;
                const float* cp = rcos + pos*64 + d;
                if (c8 < 64) {
                    #pragma unroll
                    for (int e = 0; e < 4; e++)
                        p.h[e] = __floats2half2_rn(src[e*2]   * cp[e*2]   - par[e*2]   * sp[e*2],
                                                   src[e*2+1] * cp[e*2+1] - par[e*2+1] * sp[e*2+1]);
                } else {
                    #pragma unroll
                    for (int e = 0; e < 4; e++)
                        p.h[e] = __floats2half2_rn(src[e*2]   * cp[e*2]   + par[e*2]   * sp[e*2],
                                                   src[e*2+1] * cp[e*2+1] + par[e*2+1] * sp[e*2+1]);
                }
            } else {
                #pragma unroll
                for (int e = 0; e < 4; e++)
                    p.h[e] = __floats2half2_rn(src[e*2], src[e*2+1]);
            }
            *(uint4*)((half*)C + (size_t)(bm0 + row)*ldc + col0 + c8) = p.u;
        }
    }
}

__global__ __launch_bounds__(128, 3) void gemm_kernel(
    const half* __restrict__ A, const half* __restrict__ B,
    const float* __restrict__ Res, float* __restrict__ C, int K, int N)
{
    gemm_core<float>(A, B, Res, C, K, N, N, blockIdx.y * 128, blockIdx.x * 128, nullptr, nullptr);
}

__global__ __launch_bounds__(128, 3) void qkv_kernel(
    const half* __restrict__ h,
    const half* __restrict__ wq, const half* __restrict__ wk, const half* __restrict__ wv,
    half* __restrict__ q, half* __restrict__ k, half* __restrict__ v,
    const float* __restrict__ rsin, const float* __restrict__ rcos)
{
    int bn = blockIdx.x;
    const half* B; half* C; int ldn; int c0; bool rope;
    if (bn < 8)       { B = wq; C = q; ldn = NQH*HD;  c0 = bn * 128;        rope = true;  }
    else if (bn < 10) { B = wk; C = k; ldn = NKVH*HD; c0 = (bn - 8) * 128;  rope = true;  }
    else              { B = wv; C = v; ldn = NKVH*HD; c0 = (bn - 10) * 128; rope = false; }
    gemm_core<half>(h, B, nullptr, C, DD, ldn, ldn, blockIdx.y * 128, c0,
                    rope ? rsin : nullptr, rcos);
}

// ---------------- fused gate+up GEMM with silu epilogue ----------------
#define GBP 72
#define GUA (128*APH)           // 9216 halves
#define GUB (64*GBP)            // 4608 halves
#define GUSTG (GUA + 2*GUB)     // 18432 halves
#define GUSILU_SMEM (2*GUSTG*2) // 73728 bytes

__device__ __forceinline__ void gusilu_stage_load(
    half* As, half* Bg, half* Bu,
    const half* A, const half* WG, const half* WU,
    int bm0, int col0, int k0, int tid)
{
    #pragma unroll
    for (int p = 0; p < 4; p++) {
        int idx = p * 256 + tid;
        int row = idx >> 3, c8 = (idx & 7) * 8;
        cp_async16h(As + row*APH + c8, A + (size_t)(bm0 + row)*DD + k0 + c8);
    }
    #pragma unroll
    for (int p = 0; p < 2; p++) {
        int idx = p * 256 + tid;
        int br = idx >> 3, bc8 = (idx & 7) * 8;
        cp_async16h(Bg + br*GBP + bc8, WG + (size_t)(k0 + br)*FFND + col0 + bc8);
        cp_async16h(Bu + br*GBP + bc8, WU + (size_t)(k0 + br)*FFND + col0 + bc8);
    }
    asm volatile("cp.async.commit_group;\n" ::);
}

__global__ __launch_bounds__(256, 2) void gusilu_kernel(
    const half* __restrict__ h2,
    const half* __restrict__ wg, const half* __restrict__ wu,
    half* __restrict__ act)
{
    extern __shared__ half smh[];
    int tid  = threadIdx.x;
    int warp = tid >> 5;
    int wm = warp & 3;
    int wn = warp >> 2;
    int bm0 = blockIdx.y * 128;
    int col0 = blockIdx.x * 64;

    wmma::fragment<wmma::accumulator, 16,16,16, float> accg[2][2], accu[2][2];
    #pragma unroll
    for (int i = 0; i < 2; i++)
        #pragma unroll
        for (int j = 0; j < 2; j++) {
            wmma::fill_fragment(accg[i][j], 0.0f);
            wmma::fill_fragment(accu[i][j], 0.0f);
        }

    gusilu_stage_load(smh, smh + GUA, smh + GUA + GUB, h2, wg, wu, bm0, col0, 0, tid);

    const int nk = DD >> 6;       // 16
    for (int kt = 0; kt < nk; kt++) {
        asm volatile("cp.async.wait_group 0;\n" ::);
        __syncthreads();

        if (kt + 1 < nk) {
            int s = (kt + 1) & 1;
            gusilu_stage_load(smh + s*GUSTG, smh + s*GUSTG + GUA, smh + s*GUSTG + GUA + GUB,
                              h2, wg, wu, bm0, col0, (kt + 1) << 6, tid);
        }

        half* As = smh + (kt & 1) * GUSTG;
        half* Bg = As + GUA;
        half* Bu = Bg + GUB;
        #pragma unroll
        for (int ks = 0; ks < 4; ks++) {
            wmma::fragment<wmma::matrix_a, 16,16,16, half, wmma::row_major> af[2];
            wmma::fragment<wmma::matrix_b, 16,16,16, half, wmma::row_major> bgf[2], buf[2];
            #pragma unroll
            for (int i = 0; i < 2; i++)
                wmma::load_matrix_sync(af[i], As + (wm*32 + i*16)*APH + ks*16, APH);
            #pragma unroll
            for (int j = 0; j < 2; j++) {
                wmma::load_matrix_sync(bgf[j], Bg + (ks*16)*GBP + wn*32 + j*16, GBP);
                wmma::load_matrix_sync(buf[j], Bu + (ks*16)*GBP + wn*32 + j*16, GBP);
            }
            #pragma unroll
            for (int i = 0; i < 2; i++)
                #pragma unroll
                for (int j = 0; j < 2; j++) {
                    wmma::mma_sync(accg[i][j], af[i], bgf[j], accg[i][j]);
                    wmma::mma_sync(accu[i][j], af[i], buf[j], accu[i][j]);
                }
        }
    }

    __syncthreads();
    float* sG = (float*)smh;            // [128][64]
    float* sU = sG + 128*64;            // [128][64]
    #pragma unroll
    for (int i = 0; i < 2; i++)
        #pragma unroll
        for (int j = 0; j < 2; j++) {
            wmma::store_matrix_sync(sG + (wm*32 + i*16)*64 + wn*32 + j*16, accg[i][j], 64, wmma::mem_row_major);
            wmma::store_matrix_sync(sU + (wm*32 + i*16)*64 + wn*32 + j*16, accu[i][j], 64, wmma::mem_row_major);
        }
    __syncthreads();
    #pragma unroll
    for (int it = 0; it < 4; it++) {
        int idx = it * 256 + tid;
        int row = idx >> 3, c8 = (idx & 7) * 8;
        const float* gp = sG + row*64 + c8;
        const float* up = sU + row*64 + c8;
        HPack8 p;
        #pragma unroll
        for (int e = 0; e < 4; e++) {
            float g0 = gp[e*2],   u0 = up[e*2];
            float g1 = gp[e*2+1], u1 = up[e*2+1];
            p.h[e] = __floats2half2_rn(g0 / (1.f + __expf(-g0)) * u0,
                                       g1 / (1.f + __expf(-g1)) * u1);
        }
        *(uint4*)(act + (size_t)(bm0 + row)*FFND + col0 + c8) = p.u;
    }
}

// ---------------- Flash attention: TQ=128, fp16 in/out, O in fragments ----------------
#define TQ 128
#define TK 64
#define HP 136
#define SPF 72                 // S pitch (floats, 288 B)
#define PPH 144                // P pitch (halves, 288 B) -> row-aligned alias of sS
// hQ(34816) + hK(17408) + hV(17408) + sS(128*72*4=36864) + sM/sL/sAlpha(3*128*4=1536)
#define ATTN_SMEM (TQ*HP*2 + 2*TK*HP*2 + TQ*SPF*4 + 3*TQ*4)   // 108032 bytes

__global__ __launch_bounds__(256, 2) void attn_kernel(
    const half* __restrict__ Q, const half* __restrict__ K,
    const half* __restrict__ V, half* __restrict__ O)
{
    extern __shared__ char smraw[];
    half*  hQ = (half*)smraw;                    // [128][136]
    half*  hK = hQ + TQ * HP;                    // [64][136]
    half*  hV = hK + TK * HP;                    // [64][136]
    float* sS = (float*)(hV + TK * HP);          // [128][72] fp32
    half*  sP = (half*)sS;                       // [128][144] halves (row-aligned alias)
    float* sM = sS + TQ * SPF;                   // [128]
    float* sL = sM + TQ;                         // [128]
    float* sAlpha = sL + TQ;                     // [128]

    int qt = (gridDim.x - 1) - blockIdx.x;       // heavy tiles first
    int h = blockIdx.y, b = blockIdx.z;
    int kh = h >> 2;
    int tid = threadIdx.x;
    int warp = tid >> 5, lane = tid & 31;
    int q0 = qt * TQ;
    int wr = warp & 3, wc = warp >> 2;           // QK: 4x2 warp grid; PV cols: wc*64

    // load Q tile (128 rows x 16 uint4)
    #pragma unroll
    for (int it = 0; it < 8; it++) {
        int idx = it * 256 + tid;
        int r = idx >> 4, c8 = (idx & 15) * 8;
        *(uint4*)(hQ + r * HP + c8) =
            *(const uint4*)(Q + ((size_t)((b*LL + q0 + r)*NQH + h))*HD + c8);
    }
    if (tid < TQ) { sM[tid] = -1e30f; sL[tid] = 0.f; }

    // persistent PV accumulators: warp covers rows wr*32..+31, cols wc*64..+63
    wmma::fragment<wmma::accumulator, 16,16,16, float> pacc[2][4];
    #pragma unroll
    for (int i = 0; i < 2; i++)
        #pragma unroll
        for (int j = 0; j < 4; j++)
            wmma::fill_fragment(pacc[i][j], 0.0f);

    const float scale = 0.08838834764831845f;
    int nkt = 2*qt + 2;

    for (int kt = 0; kt < nkt; kt++) {
        int kb = kt * TK;
        // K/V tiles: 64 rows x 16 uint4 each = 1024 slots -> 4 iterations of 256
        #pragma unroll
        for (int it = 0; it < 4; it++) {
            int idx = it * 256 + tid;
            int j = idx >> 4, c8 = (idx & 15) * 8;
            *(uint4*)(hK + j * HP + c8) =
                *(const uint4*)(K + ((size_t)((b*LL + kb + j)*NKVH + kh))*HD + c8);
            *(uint4*)(hV + j * HP + c8) =
                *(const uint4*)(V + ((size_t)((b*LL + kb + j)*NKVH + kh))*HD + c8);
        }
        __syncthreads();   // B

        // ---- S = Q(128xHD) @ K^T(HDx64): warp = 32 rows x 32 cols ----
        {
            wmma::fragment<wmma::accumulator, 16,16,16, float> sacc[2][2];
            #pragma unroll
            for (int i = 0; i < 2; i++)
                #pragma unroll
                for (int j = 0; j < 2; j++)
                    wmma::fill_fragment(sacc[i][j], 0.0f);
            #pragma unroll
            for (int kk = 0; kk < 8; kk++) {
                wmma::fragment<wmma::matrix_b, 16,16,16, half, wmma::col_major> bf[2];
                #pragma unroll
                for (int j = 0; j < 2; j++)
                    wmma::load_matrix_sync(bf[j], hK + (wc*32 + j*16)*HP + kk*16, HP);
                #pragma unroll
                for (int i = 0; i < 2; i++) {
                    wmma::fragment<wmma::matrix_a, 16,16,16, half, wmma::row_major> af;
                    wmma::load_matrix_sync(af, hQ + (wr*32 + i*16)*HP + kk*16, HP);
                    #pragma unroll
                    for (int j = 0; j < 2; j++)
                        wmma::mma_sync(sacc[i][j], af, bf[j], sacc[i][j]);
                }
            }
            #pragma unroll
            for (int i = 0; i < 2; i++)
                #pragma unroll
                for (int j = 0; j < 2; j++)
                    wmma::store_matrix_sync(sS + (wr*32 + i*16)*SPF + wc*32 + j*16,
                                            sacc[i][j], SPF, wmma::mem_row_major);
        }
        __syncthreads();   // C

        // ---- online softmax: warp owns rows warp*16..+15 ----
        // P (halves) is written into bytes [0,128) of the SAME row's S storage
        // (row-aligned alias, pitch 288 B both): those bytes hold s1 floats this
        // warp has already read, and no other warp touches this row before sync D.
        #pragma unroll
        for (int rr = 0; rr < 16; rr++) {
            int row = warp*16 + rr;
            int qi = q0 + row;
            float s1 = sS[row*SPF + lane];
            float s2 = sS[row*SPF + lane + 32];
            s1 = (kb + lane      <= qi) ? s1 * scale : -1e30f;
            s2 = (kb + lane + 32 <= qi) ? s2 * scale : -1e30f;
            float mx = fmaxf(s1, s2);
            #pragma unroll
            for (int off = 16; off; off >>= 1)
                mx = fmaxf(mx, __shfl_xor_sync(0xffffffffu, mx, off));
            float mold = sM[row];
            float mnew = fmaxf(mold, mx);
            float p1 = __expf(s1 - mnew);
            float p2 = __expf(s2 - mnew);
            float ps = p1 + p2;
            #pragma unroll
            for (int off = 16; off; off >>= 1)
                ps += __shfl_xor_sync(0xffffffffu, ps, off);
            float alpha = __expf(mold - mnew);
            sP[row*PPH + lane]      = __float2half(p1);
            sP[row*PPH + lane + 32] = __float2half(p2);
            if (lane == 0) {
                sM[row] = mnew;
                sAlpha[row] = alpha;
                sL[row] = sL[row] * alpha + ps;
            }
        }
        __syncthreads();   // D

        // ---- rescale pacc by alpha, then accumulate PV (P 128x64 @ V 64x128) ----
        #pragma unroll
        for (int i = 0; i < 2; i++) {
            int rowA = wr*32 + i*16 + (lane >> 2);
            float aA = sAlpha[rowA];
            float aB = sAlpha[rowA + 8];
            #pragma unroll
            for (int j = 0; j < 4; j++) {
                pacc[i][j].x[0] *= aA; pacc[i][j].x[1] *= aA;
                pacc[i][j].x[2] *= aB; pacc[i][j].x[3] *= aB;
                pacc[i][j].x[4] *= aA; pacc[i][j].x[5] *= aA;
                pacc[i][j].x[6] *= aB; pacc[i][j].x[7] *= aB;
            }
        }
        #pragma unroll
        for (int kk = 0; kk < 4; kk++) {
            wmma::fragment<wmma::matrix_a, 16,16,16, half, wmma::row_major> af[2];
            wmma::fragment<wmma::matrix_b, 16,16,16, half, wmma::row_major> bf[4];
            #pragma unroll
            for (int i = 0; i < 2; i++)
                wmma::load_matrix_sync(af[i], sP + (wr*32 + i*16)*PPH + kk*16, PPH);
            #pragma unroll
            for (int j = 0; j < 4; j++)
                wmma::load_matrix_sync(bf[j], hV + (kk*16)*HP + wc*64 + j*16, HP);
            #pragma unroll
            for (int i = 0; i < 2; i++)
                #pragma unroll
                for (int j = 0; j < 4; j++)
                    wmma::mma_sync(pacc[i][j], af[i], bf[j], pacc[i][j]);
        }
        __syncthreads();   // E
    }

    // write O from fragments, normalized by sL
    #pragma unroll
    for (int i = 0; i < 2; i++) {
        int rowA = wr*32 + i*16 + (lane >> 2);
        int rowB = rowA + 8;
        float invA = 1.0f / sL[rowA];
        float invB = 1.0f / sL[rowB];
        size_t baseA = ((size_t)((b*LL + q0 + rowA)*NQH + h))*HD;
        size_t baseB = ((size_t)((b*LL + q0 + rowB)*NQH + h))*HD;
        #pragma unroll
        for (int j = 0; j < 4; j++) {
            int c0 = wc*64 + j*16 + 2*(lane & 3);
            *(half2*)(O + baseA + c0)     = __floats2half2_rn(pacc[i][j].x[0]*invA, pacc[i][j].x[1]*invA);
            *(half2*)(O + baseB + c0)     = __floats2half2_rn(pacc[i][j].x[2]*invB, pacc[i][j].x[3]*invB);
            *(half2*)(O + baseA + c0 + 8) = __floats2half2_rn(pacc[i][j].x[4]*invA, pacc[i][j].x[5]*invA);
            *(half2*)(O + baseB + c0 + 8) = __floats2half2_rn(pacc[i][j].x[6]*invB, pacc[i][j].x[7]*invB);
        }
    }
}

// ---------------- launch ----------------
extern "C" void kernel_launch(void* const* d_in, const int* in_sizes, int n_in,
                              void* d_out, int out_size)
{
    const float* x   = (const float*)d_in[0];
    const float* ln1 = (const float*)d_in[1];
    const float* wq  = (const float*)d_in[2];
    const float* wk  = (const float*)d_in[3];
    const float* wv  = (const float*)d_in[4];
    const float* wo  = (const float*)d_in[5];
    const float* ln2 = (const float*)d_in[6];
    const float* wg  = (const float*)d_in[7];
    const float* wu  = (const float*)d_in[8];
    const float* wd  = (const float*)d_in[9];
    float* out = (float*)d_out;

    half *h, *q, *k, *v, *ctx, *h2, *act;
    float *x1, *rsin, *rcos;
    half *wqh, *wkh, *wvh, *woh, *wgh, *wuh, *wdh;
    cudaGetSymbolAddress((void**)&h,   g_h);
    cudaGetSymbolAddress((void**)&q,   g_q);
    cudaGetSymbolAddress((void**)&k,   g_k);
    cudaGetSymbolAddress((void**)&v,   g_v);
    cudaGetSymbolAddress((void**)&ctx, g_ctx);
    cudaGetSymbolAddress((void**)&x1,  g_x1);
    cudaGetSymbolAddress((void**)&h2,  g_h2);
    cudaGetSymbolAddress((void**)&act, g_act);
    cudaGetSymbolAddress((void**)&wqh, g_wqh);
    cudaGetSymbolAddress((void**)&wkh, g_wkh);
    cudaGetSymbolAddress((void**)&wvh, g_wvh);
    cudaGetSymbolAddress((void**)&woh, g_woh);
    cudaGetSymbolAddress((void**)&wgh, g_wgh);
    cudaGetSymbolAddress((void**)&wuh, g_wuh);
    cudaGetSymbolAddress((void**)&wdh, g_wdh);
    cudaGetSymbolAddress((void**)&rsin, g_rsin);
    cudaGetSymbolAddress((void**)&rcos, g_rcos);

    cudaFuncSetAttribute(attn_kernel,   cudaFuncAttributeMaxDynamicSharedMemorySize, ATTN_SMEM);
    cudaFuncSetAttribute(gemm_kernel,   cudaFuncAttributeMaxDynamicSharedMemorySize, GEMM_SMEM);
    cudaFuncSetAttribute(qkv_kernel,    cudaFuncAttributeMaxDynamicSharedMemorySize, GEMM_SMEM);
    cudaFuncSetAttribute(gusilu_kernel, cudaFuncAttributeMaxDynamicSharedMemorySize, GUSILU_SMEM);

    // 0) weights -> fp16 + rope tables
    convert_weights_kernel<<<(NCONV + 255) / 256, 256>>>(
        wq, wk, wv, wo, wg, wu, wd, wqh, wkh, wvh, woh, wgh, wuh, wdh, rsin, rcos);
    // 1) rmsnorm1 -> fp16
    rmsnorm_kernel<<<ROWS, 256>>>(x, ln1, h);
    // 2) fused qkv projections -> fp16 q,k,v (rope in epilogue)
    qkv_kernel<<<dim3(12, ROWS/128), 128, GEMM_SMEM>>>(h, wqh, wkh, wvh, q, k, v, rsin, rcos);
    // 3) attention -> fp16 ctx   <- ncu captures launch index 3
    attn_kernel<<<dim3(LL / TQ, NQH, BB), 256, ATTN_SMEM>>>(q, k, v, ctx);
    // 4) output proj + residual -> fp32 x1
    gemm_kernel<<<dim3(DD/128, ROWS/128), 128, GEMM_SMEM>>>(ctx, woh, x, x1, DD, DD);
    // 5) rmsnorm2 -> fp16
    rmsnorm_kernel<<<ROWS, 256>>>(x1, ln2, h2);
    // 6) fused gate+up+silu -> fp16 act
    gusilu_kernel<<<dim3(FFND/64, ROWS/128), 256, GUSILU_SMEM>>>(h2, wgh, wuh, act);
    // 7) down proj + residual -> out
    gemm_kernel<<<dim3(DD/128, ROWS/128), 128, GEMM_SMEM>>>(act, wdh, x1, out, FFND, DD);
}

// round 15
// speedup vs baseline: 1.0921x; 1.0921x over previous
#include <cuda_runtime.h>
#include <cuda_fp16.h>
#include <mma.h>
#include <math.h>
#include <cstdint>

using namespace nvcuda;

// Problem constants
#define BB 2
#define LL 2048
#define DD 1024
#define NQH 8
#define NKVH 2
#define HD 128
#define FFND 4096
#define ROWS (BB*LL)            // 4096
#define EPSV 1.1920929e-07f

// ---------------- scratch (device globals; no allocs allowed) ----------------
__device__ half  g_h  [ROWS*DD];        // rmsnorm1 out (fp16)
__device__ half  g_q  [ROWS*NQH*HD];    // q proj (fp16, roped in epilogue)
__device__ half  g_k  [ROWS*NKVH*HD];   // k proj (fp16, roped in epilogue)
__device__ half  g_v  [ROWS*NKVH*HD];   // v proj (fp16)
__device__ half  g_ctx[ROWS*DD];        // attention out (fp16)
__device__ float g_x1 [ROWS*DD];        // post-attn residual (fp32)
__device__ half  g_h2 [ROWS*DD];        // rmsnorm2 out (fp16)
__device__ half  g_g  [ROWS*FFND];      // gate (fp16)
__device__ half  g_u  [ROWS*FFND];      // up (fp16)
__device__ half  g_act[ROWS*FFND];      // silu*u (fp16)
// fp16 weight copies
__device__ half  g_wqh[DD*NQH*HD];
__device__ half  g_wkh[DD*NKVH*HD];
__device__ half  g_wvh[DD*NKVH*HD];
__device__ half  g_woh[DD*DD];
__device__ half  g_wgh[DD*FFND];
__device__ half  g_wuh[DD*FFND];
__device__ half  g_wdh[FFND*DD];
// rope tables (fp32)
__device__ float g_rsin[LL*64];
__device__ float g_rcos[LL*64];

// ---------------- pack helpers ----------------
union HPack { half2 h[2]; uint2 u; };
__device__ __forceinline__ uint2 pack4(float a, float b, float c, float d) {
    HPack p;
    p.h[0] = __floats2half2_rn(a, b);
    p.h[1] = __floats2half2_rn(c, d);
    return p.u;
}
union HPack8 { half2 h[4]; uint4 u; };

// ---------------- fused weight conversion + rope table (one launch) ----------------
#define N4_WQ 262144
#define N4_WK 65536
#define N4_WV 65536
#define N4_WO 262144
#define N4_WG 1048576
#define N4_WU 1048576
#define N4_WD 1048576
#define N4_TOT (N4_WQ+N4_WK+N4_WV+N4_WO+N4_WG+N4_WU+N4_WD)   // 3801088
#define NROPE (LL*64)                                         // 131072
#define NCONV (N4_TOT + NROPE)

__global__ void convert_weights_kernel(
    const float* __restrict__ wq, const float* __restrict__ wk, const float* __restrict__ wv,
    const float* __restrict__ wo, const float* __restrict__ wg, const float* __restrict__ wu,
    const float* __restrict__ wd,
    half* __restrict__ wqh, half* __restrict__ wkh, half* __restrict__ wvh,
    half* __restrict__ woh, half* __restrict__ wgh, half* __restrict__ wuh,
    half* __restrict__ wdh, float* __restrict__ rsin, float* __restrict__ rcos)
{
    int i = blockIdx.x * blockDim.x + threadIdx.x;
    if (i >= NCONV) return;
    if (i >= N4_TOT) {
        int j = i - N4_TOT;
        int pos = j >> 6, d = j & 63;
        float freq = powf(10000.0f, (float)d * (2.0f / HD));
        float rad = (float)pos / freq;
        float sn, cs;
        sincosf(rad, &sn, &cs);
        rsin[j] = sn;
        rcos[j] = cs;
        return;
    }
    const float* src; half* dst; int off = i;
    if      (off < N4_WQ)                         { src = wq; dst = wqh; }
    else if ((off -= N4_WQ) < N4_WK)              { src = wk; dst = wkh; }
    else if ((off -= N4_WK) < N4_WV)              { src = wv; dst = wvh; }
    else if ((off -= N4_WV) < N4_WO)              { src = wo; dst = woh; }
    else if ((off -= N4_WO) < N4_WG)              { src = wg; dst = wgh; }
    else if ((off -= N4_WG) < N4_WU)              { src = wu; dst = wuh; }
    else    { off -= N4_WU;                         src = wd; dst = wdh; }
    float4 v = ((const float4*)src)[off];
    ((uint2*)dst)[off] = pack4(v.x, v.y, v.z, v.w);
}

// ---------------- RMSNorm (fp32 in, fp16 out) ----------------
__global__ __launch_bounds__(256) void rmsnorm_kernel(
    const float* __restrict__ x, const float* __restrict__ w, half* __restrict__ out)
{
    int row = blockIdx.x;
    const float4* xr = (const float4*)(x + (size_t)row * DD);
    float4 v = xr[threadIdx.x];
    float s = v.x*v.x + v.y*v.y + v.z*v.z + v.w*v.w;
    #pragma unroll
    for (int off = 16; off; off >>= 1) s += __shfl_xor_sync(0xffffffffu, s, off);
    __shared__ float red[8];
    if ((threadIdx.x & 31) == 0) red[threadIdx.x >> 5] = s;
    __syncthreads();
    float tot = red[0]+red[1]+red[2]+red[3]+red[4]+red[5]+red[6]+red[7];
    float r = rsqrtf(tot * (1.0f/DD) + EPSV);
    const float4 wv = ((const float4*)w)[threadIdx.x];
    ((uint2*)(out + (size_t)row * DD))[threadIdx.x] =
        pack4(v.x*r*wv.x, v.y*r*wv.y, v.z*r*wv.z, v.w*r*wv.w);
}

// ---------------- fp16 tensor-core GEMM core ----------------
#define APH 72
#define BPH 136
#define HASZ (128*APH)
#define HBSZ (64*BPH)
#define HSTG (HASZ + HBSZ)
#define GEMM_SMEM (2*HSTG*2)    // 71680 bytes

__device__ __forceinline__ void cp_async16h(half* smem, const half* g)
{
    unsigned int s = (unsigned int)__cvta_generic_to_shared(smem);
    asm volatile("cp.async.cg.shared.global [%0], [%1], 16;\n" :: "r"(s), "l"(g));
}

__device__ __forceinline__ void gemm_stage_load(
    half* As, half* Bs, const half* A, const half* B,
    int K, int ldb, int bm0, int col0, int k0, int tid)
{
    #pragma unroll
    for (int p = 0; p < 8; p++) {
        int idx = p * 128 + tid;
        int row = idx >> 3, c8 = (idx & 7) * 8;
        cp_async16h(As + row*APH + c8, A + (size_t)(bm0 + row)*K + k0 + c8);
    }
    #pragma unroll
    for (int p = 0; p < 8; p++) {
        int idx = p * 128 + tid;
        int br = idx >> 4, bc8 = (idx & 15) * 8;
        cp_async16h(Bs + br*BPH + bc8, B + (size_t)(k0 + br)*ldb + col0 + bc8);
    }
    asm volatile("cp.async.commit_group;\n" ::);
}

template <typename OT>
__device__ __forceinline__ void gemm_core(
    const half* __restrict__ A, const half* __restrict__ B,
    const float* __restrict__ Res, OT* __restrict__ C,
    int K, int ldb, int ldc, int bm0, int col0,
    const float* __restrict__ rsin, const float* __restrict__ rcos)
{
    extern __shared__ half smh[];
    int tid  = threadIdx.x;
    int warp = tid >> 5;
    int wm = warp & 1;
    int wn = warp >> 1;

    wmma::fragment<wmma::accumulator, 16,16,16, float> acc[4][4];
    #pragma unroll
    for (int i = 0; i < 4; i++)
        #pragma unroll
        for (int j = 0; j < 4; j++)
            wmma::fill_fragment(acc[i][j], 0.0f);

    int nk = K >> 6;

    gemm_stage_load(smh, smh + HASZ, A, B, K, ldb, bm0, col0, 0, tid);

    for (int kt = 0; kt < nk; kt++) {
        asm volatile("cp.async.wait_group 0;\n" ::);
        __syncthreads();

        if (kt + 1 < nk) {
            int s = (kt + 1) & 1;
            gemm_stage_load(smh + s*HSTG, smh + s*HSTG + HASZ, A, B, K, ldb, bm0, col0, (kt + 1) << 6, tid);
        }

        half* As = smh + (kt & 1) * HSTG;
        half* Bs = As + HASZ;
        #pragma unroll
        for (int ks = 0; ks < 4; ks++) {
            wmma::fragment<wmma::matrix_a, 16,16,16, half, wmma::row_major> af[4];
            wmma::fragment<wmma::matrix_b, 16,16,16, half, wmma::row_major> bf[4];
            #pragma unroll
            for (int i = 0; i < 4; i++)
                wmma::load_matrix_sync(af[i], As + (wm*64 + i*16)*APH + ks*16, APH);
            #pragma unroll
            for (int j = 0; j < 4; j++)
                wmma::load_matrix_sync(bf[j], Bs + (ks*16)*BPH + wn*64 + j*16, BPH);
            #pragma unroll
            for (int i = 0; i < 4; i++)
                #pragma unroll
                for (int j = 0; j < 4; j++)
                    wmma::mma_sync(acc[i][j], af[i], bf[j], acc[i][j]);
        }
    }

    if constexpr (sizeof(OT) == 4) {
        #pragma unroll
        for (int i = 0; i < 4; i++) {
            int r0 = bm0 + wm*64 + i*16;
            #pragma unroll
            for (int j = 0; j < 4; j++) {
                int c0 = col0 + wn*64 + j*16;
                if (Res) {
                    wmma::fragment<wmma::accumulator, 16,16,16, float> rf;
                    wmma::load_matrix_sync(rf, Res + (size_t)r0*ldc + c0, ldc, wmma::mem_row_major);
                    #pragma unroll
                    for (int e = 0; e < rf.num_elements; e++)
                        acc[i][j].x[e] += rf.x[e];
                }
                wmma::store_matrix_sync((float*)C + (size_t)r0*ldc + c0, acc[i][j], ldc, wmma::mem_row_major);
            }
        }
    } else {
        __syncthreads();
        float* scratch = (float*)smh;
        #pragma unroll
        for (int i = 0; i < 4; i++)
            #pragma unroll
            for (int j = 0; j < 4; j++)
                wmma::store_matrix_sync(scratch + warp*4096 + (i*16)*64 + j*16,
                                        acc[i][j], 64, wmma::mem_row_major);
        __syncthreads();
        #pragma unroll
        for (int it = 0; it < 16; it++) {
            int idx = it * 128 + tid;
            int row = idx >> 4, c8 = (idx & 15) * 8;
            int wid  = (row >> 6) + ((c8 >> 6) << 1);
            const float* src = scratch + wid*4096 + (row & 63)*64 + (c8 & 63);
            HPack8 p;
            if (rsin) {
                int cpart = c8 ^ 64;
                int widp = (row >> 6) + ((cpart >> 6) << 1);
                const float* par = scratch + widp*4096 + (row & 63)*64 + (c8 & 63);
                int pos = (bm0 + row) & (LL - 1);
                int d = c8 & 63;
                const float* sp = rsin + pos*64 + d;
                const float* cp = rcos + pos*64 + d;
                if (c8 < 64) {
                    #pragma unroll
                    for (int e = 0; e < 4; e++)
                        p.h[e] = __floats2half2_rn(src[e*2]   * cp[e*2]   - par[e*2]   * sp[e*2],
                                                   src[e*2+1] * cp[e*2+1] - par[e*2+1] * sp[e*2+1]);
                } else {
                    #pragma unroll
                    for (int e = 0; e < 4; e++)
                        p.h[e] = __floats2half2_rn(src[e*2]   * cp[e*2]   + par[e*2]   * sp[e*2],
                                                   src[e*2+1] * cp[e*2+1] + par[e*2+1] * sp[e*2+1]);
                }
            } else {
                #pragma unroll
                for (int e = 0; e < 4; e++)
                    p.h[e] = __floats2half2_rn(src[e*2], src[e*2+1]);
            }
            *(uint4*)((half*)C + (size_t)(bm0 + row)*ldc + col0 + c8) = p.u;
        }
    }
}

__global__ __launch_bounds__(128, 3) void gemm_kernel(
    const half* __restrict__ A, const half* __restrict__ B,
    const float* __restrict__ Res, float* __restrict__ C, int K, int N)
{
    gemm_core<float>(A, B, Res, C, K, N, N, blockIdx.y * 128, blockIdx.x * 128, nullptr, nullptr);
}

__global__ __launch_bounds__(128, 3) void qkv_kernel(
    const half* __restrict__ h,
    const half* __restrict__ wq, const half* __restrict__ wk, const half* __restrict__ wv,
    half* __restrict__ q, half* __restrict__ k, half* __restrict__ v,
    const float* __restrict__ rsin, const float* __restrict__ rcos)
{
    int bn = blockIdx.x;
    const half* B; half* C; int ldn; int c0; bool rope;
    if (bn < 8)       { B = wq; C = q; ldn = NQH*HD;  c0 = bn * 128;        rope = true;  }
    else if (bn < 10) { B = wk; C = k; ldn = NKVH*HD; c0 = (bn - 8) * 128;  rope = true;  }
    else              { B = wv; C = v; ldn = NKVH*HD; c0 = (bn - 10) * 128; rope = false; }
    gemm_core<half>(h, B, nullptr, C, DD, ldn, ldn, blockIdx.y * 128, c0,
                    rope ? rsin : nullptr, rcos);
}

__global__ __launch_bounds__(128, 3) void gu_kernel(
    const half* __restrict__ h2,
    const half* __restrict__ wg, const half* __restrict__ wu,
    half* __restrict__ g, half* __restrict__ u)
{
    int bn = blockIdx.x;
    const half* B = (bn < 32) ? wg : wu;
    half* C       = (bn < 32) ? g  : u;
    int c0 = (bn & 31) * 128;
    gemm_core<half>(h2, B, nullptr, C, DD, FFND, FFND, blockIdx.y * 128, c0, nullptr, nullptr);
}

// ---------------- Flash attention: TQ=64, O in fragments, P aliased into S ----------------
#define TQ 64
#define TK 64
#define HP 136
#define SPF 72                 // S pitch (floats, 288 B)
#define PPH 144                // P pitch (halves, 288 B) -> row-aligned alias of sS
// hQ/hK/hV(3*64*136*2=52224) + sS(64*72*4=18432) + sAlpha/sL(2*64*4=512)
#define ATTN_SMEM (3*TQ*HP*2 + TQ*SPF*4 + 2*TQ*4)   // 71168 bytes -> 3 CTAs/SM

__global__ __launch_bounds__(256, 3) void attn_kernel(
    const half* __restrict__ Q, const half* __restrict__ K,
    const half* __restrict__ V, half* __restrict__ O)
{
    extern __shared__ char smraw[];
    half*  hQ = (half*)smraw;
    half*  hK = hQ + TQ * HP;
    half*  hV = hK + TQ * HP;
    float* sS = (float*)(hV + TQ * HP);          // [64][72] fp32
    half*  sP = (half*)sS;                       // [64][144] halves (row-aligned alias)
    float* sAlpha = sS + TQ * SPF;               // [64]
    float* sL = sAlpha + TQ;                     // [64]

    int qt = (gridDim.x - 1) - blockIdx.x;       // heavy tiles first
    int h = blockIdx.y, b = blockIdx.z;
    int kh = h >> 2;
    int tid = threadIdx.x;
    int warp = tid >> 5, lane = tid & 31;
    int q0 = qt * TQ;
    int wr = warp & 1, wc = warp >> 1;

    // load Q tile (fp16 straight copy)
    #pragma unroll
    for (int it = 0; it < 4; it++) {
        int idx = it * 256 + tid;
        int r = idx >> 4, c8 = (idx & 15) * 8;
        *(uint4*)(hQ + r * HP + c8) =
            *(const uint4*)(Q + ((size_t)((b*LL + q0 + r)*NQH + h))*HD + c8);
    }

    float m[8], l[8];
    #pragma unroll
    for (int r = 0; r < 8; r++) { m[r] = -1e30f; l[r] = 0.f; }

    // persistent PV accumulator fragments
    wmma::fragment<wmma::accumulator, 16,16,16, float> pacc[2][2];
    #pragma unroll
    for (int i = 0; i < 2; i++)
        #pragma unroll
        for (int j = 0; j < 2; j++)
            wmma::fill_fragment(pacc[i][j], 0.0f);

    const float scale = 0.08838834764831845f;

    for (int kt = 0; kt <= qt; kt++) {
        int kb = kt * TK;
        #pragma unroll
        for (int it = 0; it < 4; it++) {
            int idx = it * 256 + tid;
            int j = idx >> 4, c8 = (idx & 15) * 8;
            *(uint4*)(hK + j * HP + c8) =
                *(const uint4*)(K + ((size_t)((b*LL + kb + j)*NKVH + kh))*HD + c8);
            *(uint4*)(hV + j * HP + c8) =
                *(const uint4*)(V + ((size_t)((b*LL + kb + j)*NKVH + kh))*HD + c8);
        }
        __syncthreads();   // B

        // ---- S = Q @ K^T ----
        {
            wmma::fragment<wmma::accumulator, 16,16,16, float> sacc[2];
            wmma::fill_fragment(sacc[0], 0.0f);
            wmma::fill_fragment(sacc[1], 0.0f);
            #pragma unroll
            for (int kk = 0; kk < 8; kk++) {
                wmma::fragment<wmma::matrix_b, 16,16,16, half, wmma::col_major> bf;
                wmma::load_matrix_sync(bf, hK + (wc*16)*HP + kk*16, HP);
                #pragma unroll
                for (int i = 0; i < 2; i++) {
                    wmma::fragment<wmma::matrix_a, 16,16,16, half, wmma::row_major> af;
                    wmma::load_matrix_sync(af, hQ + (wr*32 + i*16)*HP + kk*16, HP);
                    wmma::mma_sync(sacc[i], af, bf, sacc[i]);
                }
            }
            wmma::store_matrix_sync(sS + (wr*32 +  0)*SPF + wc*16, sacc[0], SPF, wmma::mem_row_major);
            wmma::store_matrix_sync(sS + (wr*32 + 16)*SPF + wc*16, sacc[1], SPF, wmma::mem_row_major);
        }
        __syncthreads();   // C

        // ---- online softmax (warp owns rows warp*8..+7) ----
        // P (halves) written into bytes [0,128) of the SAME row's S storage
        // (row-aligned alias, 288 B pitch both): that region holds s1 floats this
        // warp already read; no other warp touches the row before sync D.
        #pragma unroll
        for (int rr = 0; rr < 8; rr++) {
            int row = warp*8 + rr;
            int qi = q0 + row;
            float s1 = sS[row*SPF + lane];
            float s2 = sS[row*SPF + lane + 32];
            s1 = (kb + lane      <= qi) ? s1 * scale : -1e30f;
            s2 = (kb + lane + 32 <= qi) ? s2 * scale : -1e30f;
            float mx = fmaxf(s1, s2);
            #pragma unroll
            for (int off = 16; off; off >>= 1)
                mx = fmaxf(mx, __shfl_xor_sync(0xffffffffu, mx, off));
            float mnew = fmaxf(m[rr], mx);
            float p1 = __expf(s1 - mnew);
            float p2 = __expf(s2 - mnew);
            float ps = p1 + p2;
            #pragma unroll
            for (int off = 16; off; off >>= 1)
                ps += __shfl_xor_sync(0xffffffffu, ps, off);
            float alpha = __expf(m[rr] - mnew);
            m[rr] = mnew;
            l[rr] = l[rr] * alpha + ps;
            sP[row*PPH + lane]      = __float2half(p1);
            sP[row*PPH + lane + 32] = __float2half(p2);
            if (lane == 0) sAlpha[row] = alpha;
        }
        __syncthreads();   // D

        // ---- rescale pacc by alpha then accumulate PV ----
        #pragma unroll
        for (int i = 0; i < 2; i++) {
            int rowA = wr*32 + i*16 + (lane >> 2);
            float aA = sAlpha[rowA];
            float aB = sAlpha[rowA + 8];
            #pragma unroll
            for (int j = 0; j < 2; j++) {
                pacc[i][j].x[0] *= aA; pacc[i][j].x[1] *= aA;
                pacc[i][j].x[2] *= aB; pacc[i][j].x[3] *= aB;
                pacc[i][j].x[4] *= aA; pacc[i][j].x[5] *= aA;
                pacc[i][j].x[6] *= aB; pacc[i][j].x[7] *= aB;
            }
        }
        #pragma unroll
        for (int kk = 0; kk < 4; kk++) {
            wmma::fragment<wmma::matrix_a, 16,16,16, half, wmma::row_major> af[2];
            wmma::fragment<wmma::matrix_b, 16,16,16, half, wmma::row_major> bf[2];
            #pragma unroll
            for (int i = 0; i < 2; i++)
                wmma::load_matrix_sync(af[i], sP + (wr*32 + i*16)*PPH + kk*16, PPH);
            #pragma unroll
            for (int j = 0; j < 2; j++)
                wmma::load_matrix_sync(bf[j], hV + (kk*16)*HP + wc*32 + j*16, HP);
            #pragma unroll
            for (int i = 0; i < 2; i++)
                #pragma unroll
                for (int j = 0; j < 2; j++)
                    wmma::mma_sync(pacc[i][j], af[i], bf[j], pacc[i][j]);
        }
        __syncthreads();   // E (protect hK/hV/sS/sAlpha reuse)
    }

    // publish l, then write O from fragments (normalize per row)
    #pragma unroll
    for (int rr = 0; rr < 8; rr++)
        if (lane == 0) sL[warp*8 + rr] = l[rr];
    __syncthreads();

    #pragma unroll
    for (int i = 0; i < 2; i++) {
        int rowA = wr*32 + i*16 + (lane >> 2);
        int rowB = rowA + 8;
        float invA = 1.0f / sL[rowA];
        float invB = 1.0f / sL[rowB];
        size_t baseA = ((size_t)((b*LL + q0 + rowA)*NQH + h))*HD;
        size_t baseB = ((size_t)((b*LL + q0 + rowB)*NQH + h))*HD;
        #pragma unroll
        for (int j = 0; j < 2; j++) {
            int c0 = wc*32 + j*16 + 2*(lane & 3);
            *(half2*)(O + baseA + c0)     = __floats2half2_rn(pacc[i][j].x[0]*invA, pacc[i][j].x[1]*invA);
            *(half2*)(O + baseB + c0)     = __floats2half2_rn(pacc[i][j].x[2]*invB, pacc[i][j].x[3]*invB);
            *(half2*)(O + baseA + c0 + 8) = __floats2half2_rn(pacc[i][j].x[4]*invA, pacc[i][j].x[5]*invA);
            *(half2*)(O + baseB + c0 + 8) = __floats2half2_rn(pacc[i][j].x[6]*invB, pacc[i][j].x[7]*invB);
        }
    }
}

// ---------------- silu(g) * u -> fp16 (fp16 in) ----------------
__global__ void silu_mul_kernel(const half* __restrict__ g, const half* __restrict__ u,
                                half* __restrict__ out, int n4)
{
    int i = blockIdx.x * blockDim.x + threadIdx.x;
    if (i >= n4) return;
    HPack gp, up;
    gp.u = ((const uint2*)g)[i];
    up.u = ((const uint2*)u)[i];
    float2 g0 = __half22float2(gp.h[0]), g1 = __half22float2(gp.h[1]);
    float2 u0 = __half22float2(up.h[0]), u1 = __half22float2(up.h[1]);
    ((uint2*)out)[i] = pack4(
        g0.x / (1.f + __expf(-g0.x)) * u0.x,
        g0.y / (1.f + __expf(-g0.y)) * u0.y,
        g1.x / (1.f + __expf(-g1.x)) * u1.x,
        g1.y / (1.f + __expf(-g1.y)) * u1.y);
}

// ---------------- launch ----------------
extern "C" void kernel_launch(void* const* d_in, const int* in_sizes, int n_in,
                              void* d_out, int out_size)
{
    const float* x   = (const float*)d_in[0];
    const float* ln1 = (const float*)d_in[1];
    const float* wq  = (const float*)d_in[2];
    const float* wk  = (const float*)d_in[3];
    const float* wv  = (const float*)d_in[4];
    const float* wo  = (const float*)d_in[5];
    const float* ln2 = (const float*)d_in[6];
    const float* wg  = (const float*)d_in[7];
    const float* wu  = (const float*)d_in[8];
    const float* wd  = (const float*)d_in[9];
    float* out = (float*)d_out;

    half *h, *q, *k, *v, *ctx, *h2, *g, *u, *act;
    float *x1, *rsin, *rcos;
    half *wqh, *wkh, *wvh, *woh, *wgh, *wuh, *wdh;
    cudaGetSymbolAddress((void**)&h,   g_h);
    cudaGetSymbolAddress((void**)&q,   g_q);
    cudaGetSymbolAddress((void**)&k,   g_k);
    cudaGetSymbolAddress((void**)&v,   g_v);
    cudaGetSymbolAddress((void**)&ctx, g_ctx);
    cudaGetSymbolAddress((void**)&x1,  g_x1);
    cudaGetSymbolAddress((void**)&h2,  g_h2);
    cudaGetSymbolAddress((void**)&g,   g_g);
    cudaGetSymbolAddress((void**)&u,   g_u);
    cudaGetSymbolAddress((void**)&act, g_act);
    cudaGetSymbolAddress((void**)&wqh, g_wqh);
    cudaGetSymbolAddress((void**)&wkh, g_wkh);
    cudaGetSymbolAddress((void**)&wvh, g_wvh);
    cudaGetSymbolAddress((void**)&woh, g_woh);
    cudaGetSymbolAddress((void**)&wgh, g_wgh);
    cudaGetSymbolAddress((void**)&wuh, g_wuh);
    cudaGetSymbolAddress((void**)&wdh, g_wdh);
    cudaGetSymbolAddress((void**)&rsin, g_rsin);
    cudaGetSymbolAddress((void**)&rcos, g_rcos);

    cudaFuncSetAttribute(attn_kernel, cudaFuncAttributeMaxDynamicSharedMemorySize, ATTN_SMEM);
    cudaFuncSetAttribute(gemm_kernel, cudaFuncAttributeMaxDynamicSharedMemorySize, GEMM_SMEM);
    cudaFuncSetAttribute(qkv_kernel,  cudaFuncAttributeMaxDynamicSharedMemorySize, GEMM_SMEM);
    cudaFuncSetAttribute(gu_kernel,   cudaFuncAttributeMaxDynamicSharedMemorySize, GEMM_SMEM);

    // 0) weights -> fp16 + rope tables
    convert_weights_kernel<<<(NCONV + 255) / 256, 256>>>(
        wq, wk, wv, wo, wg, wu, wd, wqh, wkh, wvh, woh, wgh, wuh, wdh, rsin, rcos);
    // 1) rmsnorm1 -> fp16
    rmsnorm_kernel<<<ROWS, 256>>>(x, ln1, h);
    // 2) fused qkv projections -> fp16 q,k,v (rope in epilogue)
    qkv_kernel<<<dim3(12, ROWS/128), 128, GEMM_SMEM>>>(h, wqh, wkh, wvh, q, k, v, rsin, rcos);
    // 3) attention -> fp16 ctx   <- ncu captures launch index 3
    attn_kernel<<<dim3(LL / TQ, NQH, BB), 256, ATTN_SMEM>>>(q, k, v, ctx);
    // 4) output proj + residual -> fp32 x1
    gemm_kernel<<<dim3(DD/128, ROWS/128), 128, GEMM_SMEM>>>(ctx, woh, x, x1, DD, DD);
    // 5) rmsnorm2 -> fp16
    rmsnorm_kernel<<<ROWS, 256>>>(x1, ln2, h2);
    // 6) fused ffn gate+up -> fp16 g,u
    gu_kernel<<<dim3(64, ROWS/128), 128, GEMM_SMEM>>>(h2, wgh, wuh, g, u);
    // 7) silu*mul -> fp16 act
    {
        int n4 = ROWS * FFND / 4;
        silu_mul_kernel<<<(n4 + 255) / 256, 256>>>(g, u, act, n4);
    }
    // 8) down proj + residual -> out
    gemm_kernel<<<dim3(DD/128, ROWS/128), 128, GEMM_SMEM>>>(act, wdh, x1, out, FFND, DD);
}

// round 16
// speedup vs baseline: 1.1004x; 1.0076x over previous
#include <cuda_runtime.h>
#include <cuda_fp16.h>
#include <mma.h>
#include <math.h>
#include <cstdint>

using namespace nvcuda;

// Problem constants
#define BB 2
#define LL 2048
#define DD 1024
#define NQH 8
#define NKVH 2
#define HD 128
#define FFND 4096
#define ROWS (BB*LL)            // 4096
#define EPSV 1.1920929e-07f

// ---------------- scratch (device globals; no allocs allowed) ----------------
__device__ half  g_h  [ROWS*DD];        // rmsnorm1 out (fp16)
__device__ half  g_q  [ROWS*NQH*HD];    // q proj (fp16, roped in epilogue)
__device__ half  g_k  [ROWS*NKVH*HD];   // k proj (fp16, roped in epilogue)
__device__ half  g_v  [ROWS*NKVH*HD];   // v proj (fp16)
__device__ half  g_ctx[ROWS*DD];        // attention out (fp16)
__device__ float g_x1 [ROWS*DD];        // post-attn residual (fp32)
__device__ half  g_h2 [ROWS*DD];        // rmsnorm2 out (fp16)
__device__ half  g_g  [ROWS*FFND];      // gate (fp16)
__device__ half  g_u  [ROWS*FFND];      // up (fp16)
__device__ half  g_act[ROWS*FFND];      // silu*u (fp16)
// fp16 weight copies
__device__ half  g_wqh[DD*NQH*HD];
__device__ half  g_wkh[DD*NKVH*HD];
__device__ half  g_wvh[DD*NKVH*HD];
__device__ half  g_woh[DD*DD];
__device__ half  g_wgh[DD*FFND];
__device__ half  g_wuh[DD*FFND];
__device__ half  g_wdh[FFND*DD];
// rope tables (fp32)
__device__ float g_rsin[LL*64];
__device__ float g_rcos[LL*64];

// ---------------- pack helpers ----------------
union HPack { half2 h[2]; uint2 u; };
__device__ __forceinline__ uint2 pack4(float a, float b, float c, float d) {
    HPack p;
    p.h[0] = __floats2half2_rn(a, b);
    p.h[1] = __floats2half2_rn(c, d);
    return p.u;
}
union HPack8 { half2 h[4]; uint4 u; };

// ---------------- fused: rmsnorm1 (blocks 0..ROWS-1) + weight conversion + rope tables ----------------
#define N4_WQ 262144
#define N4_WK 65536
#define N4_WV 65536
#define N4_WO 262144
#define N4_WG 1048576
#define N4_WU 1048576
#define N4_WD 1048576
#define N4_TOT (N4_WQ+N4_WK+N4_WV+N4_WO+N4_WG+N4_WU+N4_WD)   // 3801088
#define NROPE (LL*64)                                         // 131072
#define NCONV (N4_TOT + NROPE)
#define NCONV_BLOCKS ((NCONV + 255) / 256)
#define PRE_BLOCKS (ROWS + NCONV_BLOCKS)

__global__ __launch_bounds__(256) void prelude_kernel(
    const float* __restrict__ x, const float* __restrict__ ln1, half* __restrict__ h,
    const float* __restrict__ wq, const float* __restrict__ wk, const float* __restrict__ wv,
    const float* __restrict__ wo, const float* __restrict__ wg, const float* __restrict__ wu,
    const float* __restrict__ wd,
    half* __restrict__ wqh, half* __restrict__ wkh, half* __restrict__ wvh,
    half* __restrict__ woh, half* __restrict__ wgh, half* __restrict__ wuh,
    half* __restrict__ wdh, float* __restrict__ rsin, float* __restrict__ rcos)
{
    if (blockIdx.x < ROWS) {
        // rmsnorm1: one block per row
        int row = blockIdx.x;
        const float4* xr = (const float4*)(x + (size_t)row * DD);
        float4 v = xr[threadIdx.x];
        float s = v.x*v.x + v.y*v.y + v.z*v.z + v.w*v.w;
        #pragma unroll
        for (int off = 16; off; off >>= 1) s += __shfl_xor_sync(0xffffffffu, s, off);
        __shared__ float red[8];
        if ((threadIdx.x & 31) == 0) red[threadIdx.x >> 5] = s;
        __syncthreads();
        float tot = red[0]+red[1]+red[2]+red[3]+red[4]+red[5]+red[6]+red[7];
        float r = rsqrtf(tot * (1.0f/DD) + EPSV);
        const float4 wv4 = ((const float4*)ln1)[threadIdx.x];
        ((uint2*)(h + (size_t)row * DD))[threadIdx.x] =
            pack4(v.x*r*wv4.x, v.y*r*wv4.y, v.z*r*wv4.z, v.w*r*wv4.w);
        return;
    }
    int i = (blockIdx.x - ROWS) * 256 + threadIdx.x;
    if (i >= NCONV) return;
    if (i >= N4_TOT) {
        int j = i - N4_TOT;
        int pos = j >> 6, d = j & 63;
        float freq = powf(10000.0f, (float)d * (2.0f / HD));
        float rad = (float)pos / freq;
        float sn, cs;
        sincosf(rad, &sn, &cs);
        rsin[j] = sn;
        rcos[j] = cs;
        return;
    }
    const float* src; half* dst; int off = i;
    if      (off < N4_WQ)                         { src = wq; dst = wqh; }
    else if ((off -= N4_WQ) < N4_WK)              { src = wk; dst = wkh; }
    else if ((off -= N4_WK) < N4_WV)              { src = wv; dst = wvh; }
    else if ((off -= N4_WV) < N4_WO)              { src = wo; dst = woh; }
    else if ((off -= N4_WO) < N4_WG)              { src = wg; dst = wgh; }
    else if ((off -= N4_WG) < N4_WU)              { src = wu; dst = wuh; }
    else    { off -= N4_WU;                         src = wd; dst = wdh; }
    float4 v = ((const float4*)src)[off];
    ((uint2*)dst)[off] = pack4(v.x, v.y, v.z, v.w);
}

// ---------------- RMSNorm (fp32 in, fp16 out) ----------------
__global__ __launch_bounds__(256) void rmsnorm_kernel(
    const float* __restrict__ x, const float* __restrict__ w, half* __restrict__ out)
{
    int row = blockIdx.x;
    const float4* xr = (const float4*)(x + (size_t)row * DD);
    float4 v = xr[threadIdx.x];
    float s = v.x*v.x + v.y*v.y + v.z*v.z + v.w*v.w;
    #pragma unroll
    for (int off = 16; off; off >>= 1) s += __shfl_xor_sync(0xffffffffu, s, off);
    __shared__ float red[8];
    if ((threadIdx.x & 31) == 0) red[threadIdx.x >> 5] = s;
    __syncthreads();
    float tot = red[0]+red[1]+red[2]+red[3]+red[4]+red[5]+red[6]+red[7];
    float r = rsqrtf(tot * (1.0f/DD) + EPSV);
    const float4 wv = ((const float4*)w)[threadIdx.x];
    ((uint2*)(out + (size_t)row * DD))[threadIdx.x] =
        pack4(v.x*r*wv.x, v.y*r*wv.y, v.z*r*wv.z, v.w*r*wv.w);
}

// ---------------- fp16 tensor-core GEMM core ----------------
#define APH 72
#define BPH 136
#define HASZ (128*APH)
#define HBSZ (64*BPH)
#define HSTG (HASZ + HBSZ)
#define GEMM_SMEM (2*HSTG*2)    // 71680 bytes

__device__ __forceinline__ void cp_async16h(half* smem, const half* g)
{
    unsigned int s = (unsigned int)__cvta_generic_to_shared(smem);
    asm volatile("cp.async.cg.shared.global [%0], [%1], 16;\n" :: "r"(s), "l"(g));
}

__device__ __forceinline__ void gemm_stage_load(
    half* As, half* Bs, const half* A, const half* B,
    int K, int ldb, int bm0, int col0, int k0, int tid)
{
    #pragma unroll
    for (int p = 0; p < 8; p++) {
        int idx = p * 128 + tid;
        int row = idx >> 3, c8 = (idx & 7) * 8;
        cp_async16h(As + row*APH + c8, A + (size_t)(bm0 + row)*K + k0 + c8);
    }
    #pragma unroll
    for (int p = 0; p < 8; p++) {
        int idx = p * 128 + tid;
        int br = idx >> 4, bc8 = (idx & 15) * 8;
        cp_async16h(Bs + br*BPH + bc8, B + (size_t)(k0 + br)*ldb + col0 + bc8);
    }
    asm volatile("cp.async.commit_group;\n" ::);
}

template <typename OT>
__device__ __forceinline__ void gemm_core(
    const half* __restrict__ A, const half* __restrict__ B,
    const float* __restrict__ Res, OT* __restrict__ C,
    int K, int ldb, int ldc, int bm0, int col0,
    const float* __restrict__ rsin, const float* __restrict__ rcos)
{
    extern __shared__ half smh[];
    int tid  = threadIdx.x;
    int warp = tid >> 5;
    int wm = warp & 1;
    int wn = warp >> 1;

    wmma::fragment<wmma::accumulator, 16,16,16, float> acc[4][4];
    #pragma unroll
    for (int i = 0; i < 4; i++)
        #pragma unroll
        for (int j = 0; j < 4; j++)
            wmma::fill_fragment(acc[i][j], 0.0f);

    int nk = K >> 6;

    gemm_stage_load(smh, smh + HASZ, A, B, K, ldb, bm0, col0, 0, tid);

    for (int kt = 0; kt < nk; kt++) {
        asm volatile("cp.async.wait_group 0;\n" ::);
        __syncthreads();

        if (kt + 1 < nk) {
            int s = (kt + 1) & 1;
            gemm_stage_load(smh + s*HSTG, smh + s*HSTG + HASZ, A, B, K, ldb, bm0, col0, (kt + 1) << 6, tid);
        }

        half* As = smh + (kt & 1) * HSTG;
        half* Bs = As + HASZ;
        #pragma unroll
        for (int ks = 0; ks < 4; ks++) {
            wmma::fragment<wmma::matrix_a, 16,16,16, half, wmma::row_major> af[4];
            wmma::fragment<wmma::matrix_b, 16,16,16, half, wmma::row_major> bf[4];
            #pragma unroll
            for (int i = 0; i < 4; i++)
                wmma::load_matrix_sync(af[i], As + (wm*64 + i*16)*APH + ks*16, APH);
            #pragma unroll
            for (int j = 0; j < 4; j++)
                wmma::load_matrix_sync(bf[j], Bs + (ks*16)*BPH + wn*64 + j*16, BPH);
            #pragma unroll
            for (int i = 0; i < 4; i++)
                #pragma unroll
                for (int j = 0; j < 4; j++)
                    wmma::mma_sync(acc[i][j], af[i], bf[j], acc[i][j]);
        }
    }

    if constexpr (sizeof(OT) == 4) {
        #pragma unroll
        for (int i = 0; i < 4; i++) {
            int r0 = bm0 + wm*64 + i*16;
            #pragma unroll
            for (int j = 0; j < 4; j++) {
                int c0 = col0 + wn*64 + j*16;
                if (Res) {
                    wmma::fragment<wmma::accumulator, 16,16,16, float> rf;
                    wmma::load_matrix_sync(rf, Res + (size_t)r0*ldc + c0, ldc, wmma::mem_row_major);
                    #pragma unroll
                    for (int e = 0; e < rf.num_elements; e++)
                        acc[i][j].x[e] += rf.x[e];
                }
                wmma::store_matrix_sync((float*)C + (size_t)r0*ldc + c0, acc[i][j], ldc, wmma::mem_row_major);
            }
        }
    } else {
        __syncthreads();
        float* scratch = (float*)smh;
        #pragma unroll
        for (int i = 0; i < 4; i++)
            #pragma unroll
            for (int j = 0; j < 4; j++)
                wmma::store_matrix_sync(scratch + warp*4096 + (i*16)*64 + j*16,
                                        acc[i][j], 64, wmma::mem_row_major);
        __syncthreads();
        #pragma unroll
        for (int it = 0; it < 16; it++) {
            int idx = it * 128 + tid;
            int row = idx >> 4, c8 = (idx & 15) * 8;
            int wid  = (row >> 6) + ((c8 >> 6) << 1);
            const float* src = scratch + wid*4096 + (row & 63)*64 + (c8 & 63);
            HPack8 p;
            if (rsin) {
                int cpart = c8 ^ 64;
                int widp = (row >> 6) + ((cpart >> 6) << 1);
                const float* par = scratch + widp*4096 + (row & 63)*64 + (c8 & 63);
                int pos = (bm0 + row) & (LL - 1);
                int d = c8 & 63;
                const float* sp = rsin + pos*64 + d;
                const float* cp = rcos + pos*64 + d;
                if (c8 < 64) {
                    #pragma unroll
                    for (int e = 0; e < 4; e++)
                        p.h[e] = __floats2half2_rn(src[e*2]   * cp[e*2]   - par[e*2]   * sp[e*2],
                                                   src[e*2+1] * cp[e*2+1] - par[e*2+1] * sp[e*2+1]);
                } else {
                    #pragma unroll
                    for (int e = 0; e < 4; e++)
                        p.h[e] = __floats2half2_rn(src[e*2]   * cp[e*2]   + par[e*2]   * sp[e*2],
                                                   src[e*2+1] * cp[e*2+1] + par[e*2+1] * sp[e*2+1]);
                }
            } else {
                #pragma unroll
                for (int e = 0; e < 4; e++)
                    p.h[e] = __floats2half2_rn(src[e*2], src[e*2+1]);
            }
            *(uint4*)((half*)C + (size_t)(bm0 + row)*ldc + col0 + c8) = p.u;
        }
    }
}

__global__ __launch_bounds__(128, 3) void gemm_kernel(
    const half* __restrict__ A, const half* __restrict__ B,
    const float* __restrict__ Res, float* __restrict__ C, int K, int N)
{
    gemm_core<float>(A, B, Res, C, K, N, N, blockIdx.y * 128, blockIdx.x * 128, nullptr, nullptr);
}

__global__ __launch_bounds__(128, 3) void qkv_kernel(
    const half* __restrict__ h,
    const half* __restrict__ wq, const half* __restrict__ wk, const half* __restrict__ wv,
    half* __restrict__ q, half* __restrict__ k, half* __restrict__ v,
    const float* __restrict__ rsin, const float* __restrict__ rcos)
{
    int bn = blockIdx.x;
    const half* B; half* C; int ldn; int c0; bool rope;
    if (bn < 8)       { B = wq; C = q; ldn = NQH*HD;  c0 = bn * 128;        rope = true;  }
    else if (bn < 10) { B = wk; C = k; ldn = NKVH*HD; c0 = (bn - 8) * 128;  rope = true;  }
    else              { B = wv; C = v; ldn = NKVH*HD; c0 = (bn - 10) * 128; rope = false; }
    gemm_core<half>(h, B, nullptr, C, DD, ldn, ldn, blockIdx.y * 128, c0,
                    rope ? rsin : nullptr, rcos);
}

__global__ __launch_bounds__(128, 3) void gu_kernel(
    const half* __restrict__ h2,
    const half* __restrict__ wg, const half* __restrict__ wu,
    half* __restrict__ g, half* __restrict__ u)
{
    int bn = blockIdx.x;
    const half* B = (bn < 32) ? wg : wu;
    half* C       = (bn < 32) ? g  : u;
    int c0 = (bn & 31) * 128;
    gemm_core<half>(h2, B, nullptr, C, DD, FFND, FFND, blockIdx.y * 128, c0, nullptr, nullptr);
}

// ---------------- Flash attention: TQ=64, fp16 in/out, O accumulator in fragments ----------------
#define TQ 64
#define TK 64
#define HP 136
#define SP 72
#define PP 80
// hQ/hK/hV(3*17408) + sS(18432) + sP(10240) + sAlpha(256) + sL(256)
#define ATTN_SMEM (3*TQ*HP*2 + TQ*SP*4 + TQ*PP*2 + 2*TQ*4)   // 81408 bytes

__global__ __launch_bounds__(256, 2) void attn_kernel(
    const half* __restrict__ Q, const half* __restrict__ K,
    const half* __restrict__ V, half* __restrict__ O)
{
    extern __shared__ char smraw[];
    half*  hQ = (half*)smraw;
    half*  hK = hQ + TQ * HP;
    half*  hV = hK + TQ * HP;
    float* sS = (float*)(hV + TQ * HP);
    half*  sP = (half*)(sS + TQ * SP);
    float* sAlpha = (float*)(sP + TQ * PP);
    float* sL = sAlpha + TQ;

    int qt = (gridDim.x - 1) - blockIdx.x;    // heavy tiles first
    int h = blockIdx.y, b = blockIdx.z;
    int kh = h >> 2;
    int tid = threadIdx.x;
    int warp = tid >> 5, lane = tid & 31;
    int q0 = qt * TQ;
    int wr = warp & 1, wc = warp >> 1;

    // load Q tile (fp16 straight copy)
    #pragma unroll
    for (int it = 0; it < 4; it++) {
        int idx = it * 256 + tid;
        int r = idx >> 4, c8 = (idx & 15) * 8;
        *(uint4*)(hQ + r * HP + c8) =
            *(const uint4*)(Q + ((size_t)((b*LL + q0 + r)*NQH + h))*HD + c8);
    }

    float m[8], l[8];
    #pragma unroll
    for (int r = 0; r < 8; r++) { m[r] = -1e30f; l[r] = 0.f; }

    // persistent PV accumulator fragments
    wmma::fragment<wmma::accumulator, 16,16,16, float> pacc[2][2];
    #pragma unroll
    for (int i = 0; i < 2; i++)
        #pragma unroll
        for (int j = 0; j < 2; j++)
            wmma::fill_fragment(pacc[i][j], 0.0f);

    const float scale = 0.08838834764831845f;

    for (int kt = 0; kt <= qt; kt++) {
        int kb = kt * TK;
        #pragma unroll
        for (int it = 0; it < 4; it++) {
            int idx = it * 256 + tid;
            int j = idx >> 4, c8 = (idx & 15) * 8;
            *(uint4*)(hK + j * HP + c8) =
                *(const uint4*)(K + ((size_t)((b*LL + kb + j)*NKVH + kh))*HD + c8);
            *(uint4*)(hV + j * HP + c8) =
                *(const uint4*)(V + ((size_t)((b*LL + kb + j)*NKVH + kh))*HD + c8);
        }
        __syncthreads();   // B

        // ---- S = Q @ K^T ----
        {
            wmma::fragment<wmma::accumulator, 16,16,16, float> sacc[2];
            wmma::fill_fragment(sacc[0], 0.0f);
            wmma::fill_fragment(sacc[1], 0.0f);
            #pragma unroll
            for (int kk = 0; kk < 8; kk++) {
                wmma::fragment<wmma::matrix_b, 16,16,16, half, wmma::col_major> bf;
                wmma::load_matrix_sync(bf, hK + (wc*16)*HP + kk*16, HP);
                #pragma unroll
                for (int i = 0; i < 2; i++) {
                    wmma::fragment<wmma::matrix_a, 16,16,16, half, wmma::row_major> af;
                    wmma::load_matrix_sync(af, hQ + (wr*32 + i*16)*HP + kk*16, HP);
                    wmma::mma_sync(sacc[i], af, bf, sacc[i]);
                }
            }
            wmma::store_matrix_sync(sS + (wr*32 +  0)*SP + wc*16, sacc[0], SP, wmma::mem_row_major);
            wmma::store_matrix_sync(sS + (wr*32 + 16)*SP + wc*16, sacc[1], SP, wmma::mem_row_major);
        }
        __syncthreads();   // C

        // ---- online softmax (warp owns rows warp*8..+7) ----
        #pragma unroll
        for (int rr = 0; rr < 8; rr++) {
            int row = warp*8 + rr;
            int qi = q0 + row;
            float s1 = sS[row*SP + lane];
            float s2 = sS[row*SP + lane + 32];
            s1 = (kb + lane      <= qi) ? s1 * scale : -1e30f;
            s2 = (kb + lane + 32 <= qi) ? s2 * scale : -1e30f;
            float mx = fmaxf(s1, s2);
            #pragma unroll
            for (int off = 16; off; off >>= 1)
                mx = fmaxf(mx, __shfl_xor_sync(0xffffffffu, mx, off));
            float mnew = fmaxf(m[rr], mx);
            float p1 = __expf(s1 - mnew);
            float p2 = __expf(s2 - mnew);
            float ps = p1 + p2;
            #pragma unroll
            for (int off = 16; off; off >>= 1)
                ps += __shfl_xor_sync(0xffffffffu, ps, off);
            float alpha = __expf(m[rr] - mnew);
            m[rr] = mnew;
            l[rr] = l[rr] * alpha + ps;
            sP[row*PP + lane]      = __float2half(p1);
            sP[row*PP + lane + 32] = __float2half(p2);
            if (lane == 0) sAlpha[row] = alpha;
        }
        __syncthreads();   // D

        // ---- rescale pacc by alpha (per fragment row) then accumulate PV ----
        #pragma unroll
        for (int i = 0; i < 2; i++) {
            int rowA = wr*32 + i*16 + (lane >> 2);
            float aA = sAlpha[rowA];
            float aB = sAlpha[rowA + 8];
            #pragma unroll
            for (int j = 0; j < 2; j++) {
                pacc[i][j].x[0] *= aA; pacc[i][j].x[1] *= aA;
                pacc[i][j].x[2] *= aB; pacc[i][j].x[3] *= aB;
                pacc[i][j].x[4] *= aA; pacc[i][j].x[5] *= aA;
                pacc[i][j].x[6] *= aB; pacc[i][j].x[7] *= aB;
            }
        }
        #pragma unroll
        for (int kk = 0; kk < 4; kk++) {
            wmma::fragment<wmma::matrix_a, 16,16,16, half, wmma::row_major> af[2];
            wmma::fragment<wmma::matrix_b, 16,16,16, half, wmma::row_major> bf[2];
            #pragma unroll
            for (int i = 0; i < 2; i++)
                wmma::load_matrix_sync(af[i], sP + (wr*32 + i*16)*PP + kk*16, PP);
            #pragma unroll
            for (int j = 0; j < 2; j++)
                wmma::load_matrix_sync(bf[j], hV + (kk*16)*HP + wc*32 + j*16, HP);
            #pragma unroll
            for (int i = 0; i < 2; i++)
                #pragma unroll
                for (int j = 0; j < 2; j++)
                    wmma::mma_sync(pacc[i][j], af[i], bf[j], pacc[i][j]);
        }
        __syncthreads();   // E (protect hK/hV/sP/sAlpha reuse)
    }

    // publish l, then write O from fragments (normalize per row)
    #pragma unroll
    for (int rr = 0; rr < 8; rr++)
        if (lane == 0) sL[warp*8 + rr] = l[rr];
    __syncthreads();

    #pragma unroll
    for (int i = 0; i < 2; i++) {
        int rowA = wr*32 + i*16 + (lane >> 2);
        int rowB = rowA + 8;
        float invA = 1.0f / sL[rowA];
        float invB = 1.0f / sL[rowB];
        size_t baseA = ((size_t)((b*LL + q0 + rowA)*NQH + h))*HD;
        size_t baseB = ((size_t)((b*LL + q0 + rowB)*NQH + h))*HD;
        #pragma unroll
        for (int j = 0; j < 2; j++) {
            int c0 = wc*32 + j*16 + 2*(lane & 3);
            *(half2*)(O + baseA + c0)     = __floats2half2_rn(pacc[i][j].x[0]*invA, pacc[i][j].x[1]*invA);
            *(half2*)(O + baseB + c0)     = __floats2half2_rn(pacc[i][j].x[2]*invB, pacc[i][j].x[3]*invB);
            *(half2*)(O + baseA + c0 + 8) = __floats2half2_rn(pacc[i][j].x[4]*invA, pacc[i][j].x[5]*invA);
            *(half2*)(O + baseB + c0 + 8) = __floats2half2_rn(pacc[i][j].x[6]*invB, pacc[i][j].x[7]*invB);
        }
    }
}

// ---------------- silu(g) * u -> fp16 (fp16 in) ----------------
__global__ void silu_mul_kernel(const half* __restrict__ g, const half* __restrict__ u,
                                half* __restrict__ out, int n4)
{
    int i = blockIdx.x * blockDim.x + threadIdx.x;
    if (i >= n4) return;
    HPack gp, up;
    gp.u = ((const uint2*)g)[i];
    up.u = ((const uint2*)u)[i];
    float2 g0 = __half22float2(gp.h[0]), g1 = __half22float2(gp.h[1]);
    float2 u0 = __half22float2(up.h[0]), u1 = __half22float2(up.h[1]);
    ((uint2*)out)[i] = pack4(
        g0.x / (1.f + __expf(-g0.x)) * u0.x,
        g0.y / (1.f + __expf(-g0.y)) * u0.y,
        g1.x / (1.f + __expf(-g1.x)) * u1.x,
        g1.y / (1.f + __expf(-g1.y)) * u1.y);
}

// ---------------- launch ----------------
extern "C" void kernel_launch(void* const* d_in, const int* in_sizes, int n_in,
                              void* d_out, int out_size)
{
    const float* x   = (const float*)d_in[0];
    const float* ln1 = (const float*)d_in[1];
    const float* wq  = (const float*)d_in[2];
    const float* wk  = (const float*)d_in[3];
    const float* wv  = (const float*)d_in[4];
    const float* wo  = (const float*)d_in[5];
    const float* ln2 = (const float*)d_in[6];
    const float* wg  = (const float*)d_in[7];
    const float* wu  = (const float*)d_in[8];
    const float* wd  = (const float*)d_in[9];
    float* out = (float*)d_out;

    half *h, *q, *k, *v, *ctx, *h2, *g, *u, *act;
    float *x1, *rsin, *rcos;
    half *wqh, *wkh, *wvh, *woh, *wgh, *wuh, *wdh;
    cudaGetSymbolAddress((void**)&h,   g_h);
    cudaGetSymbolAddress((void**)&q,   g_q);
    cudaGetSymbolAddress((void**)&k,   g_k);
    cudaGetSymbolAddress((void**)&v,   g_v);
    cudaGetSymbolAddress((void**)&ctx, g_ctx);
    cudaGetSymbolAddress((void**)&x1,  g_x1);
    cudaGetSymbolAddress((void**)&h2,  g_h2);
    cudaGetSymbolAddress((void**)&g,   g_g);
    cudaGetSymbolAddress((void**)&u,   g_u);
    cudaGetSymbolAddress((void**)&act, g_act);
    cudaGetSymbolAddress((void**)&wqh, g_wqh);
    cudaGetSymbolAddress((void**)&wkh, g_wkh);
    cudaGetSymbolAddress((void**)&wvh, g_wvh);
    cudaGetSymbolAddress((void**)&woh, g_woh);
    cudaGetSymbolAddress((void**)&wgh, g_wgh);
    cudaGetSymbolAddress((void**)&wuh, g_wuh);
    cudaGetSymbolAddress((void**)&wdh, g_wdh);
    cudaGetSymbolAddress((void**)&rsin, g_rsin);
    cudaGetSymbolAddress((void**)&rcos, g_rcos);

    cudaFuncSetAttribute(attn_kernel, cudaFuncAttributeMaxDynamicSharedMemorySize, ATTN_SMEM);
    cudaFuncSetAttribute(gemm_kernel, cudaFuncAttributeMaxDynamicSharedMemorySize, GEMM_SMEM);
    cudaFuncSetAttribute(qkv_kernel,  cudaFuncAttributeMaxDynamicSharedMemorySize, GEMM_SMEM);
    cudaFuncSetAttribute(gu_kernel,   cudaFuncAttributeMaxDynamicSharedMemorySize, GEMM_SMEM);

    // 0) fused: rmsnorm1 + weights->fp16 + rope tables
    prelude_kernel<<<PRE_BLOCKS, 256>>>(
        x, ln1, h,
        wq, wk, wv, wo, wg, wu, wd,
        wqh, wkh, wvh, woh, wgh, wuh, wdh, rsin, rcos);
    // 1) fused qkv projections -> fp16 q,k,v (rope in epilogue)
    qkv_kernel<<<dim3(12, ROWS/128), 128, GEMM_SMEM>>>(h, wqh, wkh, wvh, q, k, v, rsin, rcos);
    // 2) attention -> fp16 ctx
    attn_kernel<<<dim3(LL / TQ, NQH, BB), 256, ATTN_SMEM>>>(q, k, v, ctx);
    // 3) output proj + residual -> fp32 x1   <- ncu capture lands here
    gemm_kernel<<<dim3(DD/128, ROWS/128), 128, GEMM_SMEM>>>(ctx, woh, x, x1, DD, DD);
    // 4) rmsnorm2 -> fp16
    rmsnorm_kernel<<<ROWS, 256>>>(x1, ln2, h2);
    // 5) fused ffn gate+up -> fp16 g,u
    gu_kernel<<<dim3(64, ROWS/128), 128, GEMM_SMEM>>>(h2, wgh, wuh, g, u);
    // 6) silu*mul -> fp16 act
    {
        int n4 = ROWS * FFND / 4;
        silu_mul_kernel<<<(n4 + 255) / 256, 256>>>(g, u, act, n4);
    }
    // 7) down proj + residual -> out
    gemm_kernel<<<dim3(DD/128, ROWS/128), 128, GEMM_SMEM>>>(act, wdh, x1, out, FFND, DD);
}

// round 17
// speedup vs baseline: 1.1344x; 1.0309x over previous
#include <cuda_runtime.h>
#include <cuda_fp16.h>
#include <mma.h>
#include <math.h>
#include <cstdint>

using namespace nvcuda;

// Problem constants
#define BB 2
#define LL 2048
#define DD 1024
#define NQH 8
#define NKVH 2
#define HD 128
#define FFND 4096
#define ROWS (BB*LL)            // 4096
#define EPSV 1.1920929e-07f

// ---------------- scratch (device globals; no allocs allowed) ----------------
__device__ half  g_h  [ROWS*DD];
__device__ half  g_q  [ROWS*NQH*HD];
__device__ half  g_k  [ROWS*NKVH*HD];
__device__ half  g_v  [ROWS*NKVH*HD];
__device__ half  g_ctx[ROWS*DD];
__device__ float g_x1 [ROWS*DD];
__device__ half  g_h2 [ROWS*DD];
__device__ half  g_g  [ROWS*FFND];
__device__ half  g_u  [ROWS*FFND];
__device__ half  g_act[ROWS*FFND];
__device__ half  g_wqh[DD*NQH*HD];
__device__ half  g_wkh[DD*NKVH*HD];
__device__ half  g_wvh[DD*NKVH*HD];
__device__ half  g_woh[DD*DD];
__device__ half  g_wgh[DD*FFND];
__device__ half  g_wuh[DD*FFND];
__device__ half  g_wdh[FFND*DD];
__device__ float g_rsin[LL*64];
__device__ float g_rcos[LL*64];

// ---------------- pack helpers ----------------
union HPack { half2 h[2]; uint2 u; };
__device__ __forceinline__ uint2 pack4(float a, float b, float c, float d) {
    HPack p;
    p.h[0] = __floats2half2_rn(a, b);
    p.h[1] = __floats2half2_rn(c, d);
    return p.u;
}
union HPack8 { half2 h[4]; uint4 u; };

// ---------------- fused: rmsnorm1 + weight conversion + rope tables ----------------
#define N4_WQ 262144
#define N4_WK 65536
#define N4_WV 65536
#define N4_WO 262144
#define N4_WG 1048576
#define N4_WU 1048576
#define N4_WD 1048576
#define N4_TOT (N4_WQ+N4_WK+N4_WV+N4_WO+N4_WG+N4_WU+N4_WD)   // 3801088
#define NROPE (LL*64)
#define NCONV (N4_TOT + NROPE)
#define NCONV_BLOCKS ((NCONV + 255) / 256)
#define PRE_BLOCKS (ROWS + NCONV_BLOCKS)

__global__ __launch_bounds__(256) void prelude_kernel(
    const float* __restrict__ x, const float* __restrict__ ln1, half* __restrict__ h,
    const float* __restrict__ wq, const float* __restrict__ wk, const float* __restrict__ wv,
    const float* __restrict__ wo, const float* __restrict__ wg, const float* __restrict__ wu,
    const float* __restrict__ wd,
    half* __restrict__ wqh, half* __restrict__ wkh, half* __restrict__ wvh,
    half* __restrict__ woh, half* __restrict__ wgh, half* __restrict__ wuh,
    half* __restrict__ wdh, float* __restrict__ rsin, float* __restrict__ rcos)
{
    if (blockIdx.x < ROWS) {
        int row = blockIdx.x;
        const float4* xr = (const float4*)(x + (size_t)row * DD);
        float4 v = xr[threadIdx.x];
        float s = v.x*v.x + v.y*v.y + v.z*v.z + v.w*v.w;
        #pragma unroll
        for (int off = 16; off; off >>= 1) s += __shfl_xor_sync(0xffffffffu, s, off);
        __shared__ float red[8];
        if ((threadIdx.x & 31) == 0) red[threadIdx.x >> 5] = s;
        __syncthreads();
        float tot = red[0]+red[1]+red[2]+red[3]+red[4]+red[5]+red[6]+red[7];
        float r = rsqrtf(tot * (1.0f/DD) + EPSV);
        const float4 wv4 = ((const float4*)ln1)[threadIdx.x];
        ((uint2*)(h + (size_t)row * DD))[threadIdx.x] =
            pack4(v.x*r*wv4.x, v.y*r*wv4.y, v.z*r*wv4.z, v.w*r*wv4.w);
        return;
    }
    int i = (blockIdx.x - ROWS) * 256 + threadIdx.x;
    if (i >= NCONV) return;
    if (i >= N4_TOT) {
        int j = i - N4_TOT;
        int pos = j >> 6, d = j & 63;
        float freq = powf(10000.0f, (float)d * (2.0f / HD));
        float rad = (float)pos / freq;
        float sn, cs;
        sincosf(rad, &sn, &cs);
        rsin[j] = sn;
        rcos[j] = cs;
        return;
    }
    const float* src; half* dst; int off = i;
    if      (off < N4_WQ)                         { src = wq; dst = wqh; }
    else if ((off -= N4_WQ) < N4_WK)              { src = wk; dst = wkh; }
    else if ((off -= N4_WK) < N4_WV)              { src = wv; dst = wvh; }
    else if ((off -= N4_WV) < N4_WO)              { src = wo; dst = woh; }
    else if ((off -= N4_WO) < N4_WG)              { src = wg; dst = wgh; }
    else if ((off -= N4_WG) < N4_WU)              { src = wu; dst = wuh; }
    else    { off -= N4_WU;                         src = wd; dst = wdh; }
    float4 v = ((const float4*)src)[off];
    ((uint2*)dst)[off] = pack4(v.x, v.y, v.z, v.w);
}

// ---------------- RMSNorm (fp32 in, fp16 out) ----------------
__global__ __launch_bounds__(256) void rmsnorm_kernel(
    const float* __restrict__ x, const float* __restrict__ w, half* __restrict__ out)
{
    int row = blockIdx.x;
    const float4* xr = (const float4*)(x + (size_t)row * DD);
    float4 v = xr[threadIdx.x];
    float s = v.x*v.x + v.y*v.y + v.z*v.z + v.w*v.w;
    #pragma unroll
    for (int off = 16; off; off >>= 1) s += __shfl_xor_sync(0xffffffffu, s, off);
    __shared__ float red[8];
    if ((threadIdx.x & 31) == 0) red[threadIdx.x >> 5] = s;
    __syncthreads();
    float tot = red[0]+red[1]+red[2]+red[3]+red[4]+red[5]+red[6]+red[7];
    float r = rsqrtf(tot * (1.0f/DD) + EPSV);
    const float4 wv = ((const float4*)w)[threadIdx.x];
    ((uint2*)(out + (size_t)row * DD))[threadIdx.x] =
        pack4(v.x*r*wv.x, v.y*r*wv.y, v.z*r*wv.z, v.w*r*wv.w);
}

// ---------------- fp16 tensor-core GEMM core (128-row tiles) ----------------
#define APH 72
#define BPH 136
#define HASZ (128*APH)
#define HBSZ (64*BPH)
#define HSTG (HASZ + HBSZ)
#define GEMM_SMEM (2*HSTG*2)    // 71680 bytes

__device__ __forceinline__ void cp_async16h(half* smem, const half* g)
{
    unsigned int s = (unsigned int)__cvta_generic_to_shared(smem);
    asm volatile("cp.async.cg.shared.global [%0], [%1], 16;\n" :: "r"(s), "l"(g));
}

__device__ __forceinline__ void gemm_stage_load(
    half* As, half* Bs, const half* A, const half* B,
    int K, int ldb, int bm0, int col0, int k0, int tid)
{
    #pragma unroll
    for (int p = 0; p < 8; p++) {
        int idx = p * 128 + tid;
        int row = idx >> 3, c8 = (idx & 7) * 8;
        cp_async16h(As + row*APH + c8, A + (size_t)(bm0 + row)*K + k0 + c8);
    }
    #pragma unroll
    for (int p = 0; p < 8; p++) {
        int idx = p * 128 + tid;
        int br = idx >> 4, bc8 = (idx & 15) * 8;
        cp_async16h(Bs + br*BPH + bc8, B + (size_t)(k0 + br)*ldb + col0 + bc8);
    }
    asm volatile("cp.async.commit_group;\n" ::);
}

template <typename OT>
__device__ __forceinline__ void gemm_core(
    const half* __restrict__ A, const half* __restrict__ B,
    const float* __restrict__ Res, OT* __restrict__ C,
    int K, int ldb, int ldc, int bm0, int col0,
    const float* __restrict__ rsin, const float* __restrict__ rcos)
{
    extern __shared__ half smh[];
    int tid  = threadIdx.x;
    int warp = tid >> 5;
    int wm = warp & 1;
    int wn = warp >> 1;

    wmma::fragment<wmma::accumulator, 16,16,16, float> acc[4][4];
    #pragma unroll
    for (int i = 0; i < 4; i++)
        #pragma unroll
        for (int j = 0; j < 4; j++)
            wmma::fill_fragment(acc[i][j], 0.0f);

    int nk = K >> 6;

    gemm_stage_load(smh, smh + HASZ, A, B, K, ldb, bm0, col0, 0, tid);

    for (int kt = 0; kt < nk; kt++) {
        asm volatile("cp.async.wait_group 0;\n" ::);
        __syncthreads();

        if (kt + 1 < nk) {
            int s = (kt + 1) & 1;
            gemm_stage_load(smh + s*HSTG, smh + s*HSTG + HASZ, A, B, K, ldb, bm0, col0, (kt + 1) << 6, tid);
        }

        half* As = smh + (kt & 1) * HSTG;
        half* Bs = As + HASZ;
        #pragma unroll
        for (int ks = 0; ks < 4; ks++) {
            wmma::fragment<wmma::matrix_a, 16,16,16, half, wmma::row_major> af[4];
            wmma::fragment<wmma::matrix_b, 16,16,16, half, wmma::row_major> bf[4];
            #pragma unroll
            for (int i = 0; i < 4; i++)
                wmma::load_matrix_sync(af[i], As + (wm*64 + i*16)*APH + ks*16, APH);
            #pragma unroll
            for (int j = 0; j < 4; j++)
                wmma::load_matrix_sync(bf[j], Bs + (ks*16)*BPH + wn*64 + j*16, BPH);
            #pragma unroll
            for (int i = 0; i < 4; i++)
                #pragma unroll
                for (int j = 0; j < 4; j++)
                    wmma::mma_sync(acc[i][j], af[i], bf[j], acc[i][j]);
        }
    }

    if constexpr (sizeof(OT) == 4) {
        #pragma unroll
        for (int i = 0; i < 4; i++) {
            int r0 = bm0 + wm*64 + i*16;
            #pragma unroll
            for (int j = 0; j < 4; j++) {
                int c0 = col0 + wn*64 + j*16;
                if (Res) {
                    wmma::fragment<wmma::accumulator, 16,16,16, float> rf;
                    wmma::load_matrix_sync(rf, Res + (size_t)r0*ldc + c0, ldc, wmma::mem_row_major);
                    #pragma unroll
                    for (int e = 0; e < rf.num_elements; e++)
                        acc[i][j].x[e] += rf.x[e];
                }
                wmma::store_matrix_sync((float*)C + (size_t)r0*ldc + c0, acc[i][j], ldc, wmma::mem_row_major);
            }
        }
    } else {
        __syncthreads();
        float* scratch = (float*)smh;
        #pragma unroll
        for (int i = 0; i < 4; i++)
            #pragma unroll
            for (int j = 0; j < 4; j++)
                wmma::store_matrix_sync(scratch + warp*4096 + (i*16)*64 + j*16,
                                        acc[i][j], 64, wmma::mem_row_major);
        __syncthreads();
        #pragma unroll
        for (int it = 0; it < 16; it++) {
            int idx = it * 128 + tid;
            int row = idx >> 4, c8 = (idx & 15) * 8;
            int wid  = (row >> 6) + ((c8 >> 6) << 1);
            const float* src = scratch + wid*4096 + (row & 63)*64 + (c8 & 63);
            HPack8 p;
            if (rsin) {
                int cpart = c8 ^ 64;
                int widp = (row >> 6) + ((cpart >> 6) << 1);
                const float* par = scratch + widp*4096 + (row & 63)*64 + (c8 & 63);
                int pos = (bm0 + row) & (LL - 1);
                int d = c8 & 63;
                const float* sp = rsin + pos*64 + d;
                const float* cp = rcos + pos*64 + d;
                if (c8 < 64) {
                    #pragma unroll
                    for (int e = 0; e < 4; e++)
                        p.h[e] = __floats2half2_rn(src[e*2]   * cp[e*2]   - par[e*2]   * sp[e*2],
                                                   src[e*2+1] * cp[e*2+1] - par[e*2+1] * sp[e*2+1]);
                } else {
                    #pragma unroll
                    for (int e = 0; e < 4; e++)
                        p.h[e] = __floats2half2_rn(src[e*2]   * cp[e*2]   + par[e*2]   * sp[e*2],
                                                   src[e*2+1] * cp[e*2+1] + par[e*2+1] * sp[e*2+1]);
                }
            } else {
                #pragma unroll
                for (int e = 0; e < 4; e++)
                    p.h[e] = __floats2half2_rn(src[e*2], src[e*2+1]);
            }
            *(uint4*)((half*)C + (size_t)(bm0 + row)*ldc + col0 + c8) = p.u;
        }
    }
}

__global__ __launch_bounds__(128, 3) void qkv_kernel(
    const half* __restrict__ h,
    const half* __restrict__ wq, const half* __restrict__ wk, const half* __restrict__ wv,
    half* __restrict__ q, half* __restrict__ k, half* __restrict__ v,
    const float* __restrict__ rsin, const float* __restrict__ rcos)
{
    int bn = blockIdx.x;
    const half* B; half* C; int ldn; int c0; bool rope;
    if (bn < 8)       { B = wq; C = q; ldn = NQH*HD;  c0 = bn * 128;        rope = true;  }
    else if (bn < 10) { B = wk; C = k; ldn = NKVH*HD; c0 = (bn - 8) * 128;  rope = true;  }
    else              { B = wv; C = v; ldn = NKVH*HD; c0 = (bn - 10) * 128; rope = false; }
    gemm_core<half>(h, B, nullptr, C, DD, ldn, ldn, blockIdx.y * 128, c0,
                    rope ? rsin : nullptr, rcos);
}

__global__ __launch_bounds__(128, 3) void gu_kernel(
    const half* __restrict__ h2,
    const half* __restrict__ wg, const half* __restrict__ wu,
    half* __restrict__ g, half* __restrict__ u)
{
    int bn = blockIdx.x;
    const half* B = (bn < 32) ? wg : wu;
    half* C       = (bn < 32) ? g  : u;
    int c0 = (bn & 31) * 128;
    gemm_core<half>(h2, B, nullptr, C, DD, FFND, FFND, blockIdx.y * 128, c0, nullptr, nullptr);
}

// ---------------- 64-row-tile GEMM (fp32 out + residual) for wo/wd ----------------
// Tile 64x128, 128 threads, 4 warps (32x64 each), 2-stage cp.async, 4 CTAs/SM
#define A64SZ (64*APH)            // 4608 halves
#define STG64 (A64SZ + HBSZ)      // 13312 halves
#define GEMM64_SMEM (2*STG64*2)   // 53248 bytes

__device__ __forceinline__ void gemm64_stage_load(
    half* As, half* Bs, const half* A, const half* B,
    int K, int ldb, int bm0, int col0, int k0, int tid)
{
    #pragma unroll
    for (int p = 0; p < 4; p++) {
        int idx = p * 128 + tid;
        int row = idx >> 3, c8 = (idx & 7) * 8;
        cp_async16h(As + row*APH + c8, A + (size_t)(bm0 + row)*K + k0 + c8);
    }
    #pragma unroll
    for (int p = 0; p < 8; p++) {
        int idx = p * 128 + tid;
        int br = idx >> 4, bc8 = (idx & 15) * 8;
        cp_async16h(Bs + br*BPH + bc8, B + (size_t)(k0 + br)*ldb + col0 + bc8);
    }
    asm volatile("cp.async.commit_group;\n" ::);
}

__global__ __launch_bounds__(128, 4) void gemm64_kernel(
    const half* __restrict__ A, const half* __restrict__ B,
    const float* __restrict__ Res, float* __restrict__ C, int K, int N)
{
    extern __shared__ half smh[];
    int tid  = threadIdx.x;
    int warp = tid >> 5;
    int wm = warp & 1;            // 32-row slab
    int wn = warp >> 1;           // 64-col slab
    int bm0 = blockIdx.y * 64;
    int col0 = blockIdx.x * 128;

    wmma::fragment<wmma::accumulator, 16,16,16, float> acc[2][4];
    #pragma unroll
    for (int i = 0; i < 2; i++)
        #pragma unroll
        for (int j = 0; j < 4; j++)
            wmma::fill_fragment(acc[i][j], 0.0f);

    int nk = K >> 6;

    gemm64_stage_load(smh, smh + A64SZ, A, B, K, N, bm0, col0, 0, tid);

    for (int kt = 0; kt < nk; kt++) {
        asm volatile("cp.async.wait_group 0;\n" ::);
        __syncthreads();

        if (kt + 1 < nk) {
            int s = (kt + 1) & 1;
            gemm64_stage_load(smh + s*STG64, smh + s*STG64 + A64SZ, A, B, K, N, bm0, col0, (kt + 1) << 6, tid);
        }

        half* As = smh + (kt & 1) * STG64;
        half* Bs = As + A64SZ;
        #pragma unroll
        for (int ks = 0; ks < 4; ks++) {
            wmma::fragment<wmma::matrix_a, 16,16,16, half, wmma::row_major> af[2];
            wmma::fragment<wmma::matrix_b, 16,16,16, half, wmma::row_major> bf[4];
            #pragma unroll
            for (int i = 0; i < 2; i++)
                wmma::load_matrix_sync(af[i], As + (wm*32 + i*16)*APH + ks*16, APH);
            #pragma unroll
            for (int j = 0; j < 4; j++)
                wmma::load_matrix_sync(bf[j], Bs + (ks*16)*BPH + wn*64 + j*16, BPH);
            #pragma unroll
            for (int i = 0; i < 2; i++)
                #pragma unroll
                for (int j = 0; j < 4; j++)
                    wmma::mma_sync(acc[i][j], af[i], bf[j], acc[i][j]);
        }
    }

    #pragma unroll
    for (int i = 0; i < 2; i++) {
        int r0 = bm0 + wm*32 + i*16;
        #pragma unroll
        for (int j = 0; j < 4; j++) {
            int c0 = col0 + wn*64 + j*16;
            wmma::fragment<wmma::accumulator, 16,16,16, float> rf;
            wmma::load_matrix_sync(rf, Res + (size_t)r0*N + c0, N, wmma::mem_row_major);
            #pragma unroll
            for (int e = 0; e < rf.num_elements; e++)
                acc[i][j].x[e] += rf.x[e];
            wmma::store_matrix_sync(C + (size_t)r0*N + c0, acc[i][j], N, wmma::mem_row_major);
        }
    }
}

// ---------------- Flash attention: TQ=64, fp16 in/out, O accumulator in fragments ----------------
#define TQ 64
#define TK 64
#define HP 136
#define SP 72
#define PP 80
#define ATTN_SMEM (3*TQ*HP*2 + TQ*SP*4 + TQ*PP*2 + 2*TQ*4)   // 81408 bytes

__global__ __launch_bounds__(256, 2) void attn_kernel(
    const half* __restrict__ Q, const half* __restrict__ K,
    const half* __restrict__ V, half* __restrict__ O)
{
    extern __shared__ char smraw[];
    half*  hQ = (half*)smraw;
    half*  hK = hQ + TQ * HP;
    half*  hV = hK + TQ * HP;
    float* sS = (float*)(hV + TQ * HP);
    half*  sP = (half*)(sS + TQ * SP);
    float* sAlpha = (float*)(sP + TQ * PP);
    float* sL = sAlpha + TQ;

    int qt = (gridDim.x - 1) - blockIdx.x;
    int h = blockIdx.y, b = blockIdx.z;
    int kh = h >> 2;
    int tid = threadIdx.x;
    int warp = tid >> 5, lane = tid & 31;
    int q0 = qt * TQ;
    int wr = warp & 1, wc = warp >> 1;

    #pragma unroll
    for (int it = 0; it < 4; it++) {
        int idx = it * 256 + tid;
        int r = idx >> 4, c8 = (idx & 15) * 8;
        *(uint4*)(hQ + r * HP + c8) =
            *(const uint4*)(Q + ((size_t)((b*LL + q0 + r)*NQH + h))*HD + c8);
    }

    float m[8], l[8];
    #pragma unroll
    for (int r = 0; r < 8; r++) { m[r] = -1e30f; l[r] = 0.f; }

    wmma::fragment<wmma::accumulator, 16,16,16, float> pacc[2][2];
    #pragma unroll
    for (int i = 0; i < 2; i++)
        #pragma unroll
        for (int j = 0; j < 2; j++)
            wmma::fill_fragment(pacc[i][j], 0.0f);

    const float scale = 0.08838834764831845f;

    for (int kt = 0; kt <= qt; kt++) {
        int kb = kt * TK;
        #pragma unroll
        for (int it = 0; it < 4; it++) {
            int idx = it * 256 + tid;
            int j = idx >> 4, c8 = (idx & 15) * 8;
            *(uint4*)(hK + j * HP + c8) =
                *(const uint4*)(K + ((size_t)((b*LL + kb + j)*NKVH + kh))*HD + c8);
            *(uint4*)(hV + j * HP + c8) =
                *(const uint4*)(V + ((size_t)((b*LL + kb + j)*NKVH + kh))*HD + c8);
        }
        __syncthreads();   // B

        {
            wmma::fragment<wmma::accumulator, 16,16,16, float> sacc[2];
            wmma::fill_fragment(sacc[0], 0.0f);
            wmma::fill_fragment(sacc[1], 0.0f);
            #pragma unroll
            for (int kk = 0; kk < 8; kk++) {
                wmma::fragment<wmma::matrix_b, 16,16,16, half, wmma::col_major> bf;
                wmma::load_matrix_sync(bf, hK + (wc*16)*HP + kk*16, HP);
                #pragma unroll
                for (int i = 0; i < 2; i++) {
                    wmma::fragment<wmma::matrix_a, 16,16,16, half, wmma::row_major> af;
                    wmma::load_matrix_sync(af, hQ + (wr*32 + i*16)*HP + kk*16, HP);
                    wmma::mma_sync(sacc[i], af, bf, sacc[i]);
                }
            }
            wmma::store_matrix_sync(sS + (wr*32 +  0)*SP + wc*16, sacc[0], SP, wmma::mem_row_major);
            wmma::store_matrix_sync(sS + (wr*32 + 16)*SP + wc*16, sacc[1], SP, wmma::mem_row_major);
        }
        __syncthreads();   // C

        #pragma unroll
        for (int rr = 0; rr < 8; rr++) {
            int row = warp*8 + rr;
            int qi = q0 + row;
            float s1 = sS[row*SP + lane];
            float s2 = sS[row*SP + lane + 32];
            s1 = (kb + lane      <= qi) ? s1 * scale : -1e30f;
            s2 = (kb + lane + 32 <= qi) ? s2 * scale : -1e30f;
            float mx = fmaxf(s1, s2);
            #pragma unroll
            for (int off = 16; off; off >>= 1)
                mx = fmaxf(mx, __shfl_xor_sync(0xffffffffu, mx, off));
            float mnew = fmaxf(m[rr], mx);
            float p1 = __expf(s1 - mnew);
            float p2 = __expf(s2 - mnew);
            float ps = p1 + p2;
            #pragma unroll
            for (int off = 16; off; off >>= 1)
                ps += __shfl_xor_sync(0xffffffffu, ps, off);
            float alpha = __expf(m[rr] - mnew);
            m[rr] = mnew;
            l[rr] = l[rr] * alpha + ps;
            sP[row*PP + lane]      = __float2half(p1);
            sP[row*PP + lane + 32] = __float2half(p2);
            if (lane == 0) sAlpha[row] = alpha;
        }
        __syncthreads();   // D

        #pragma unroll
        for (int i = 0; i < 2; i++) {
            int rowA = wr*32 + i*16 + (lane >> 2);
            float aA = sAlpha[rowA];
            float aB = sAlpha[rowA + 8];
            #pragma unroll
            for (int j = 0; j < 2; j++) {
                pacc[i][j].x[0] *= aA; pacc[i][j].x[1] *= aA;
                pacc[i][j].x[2] *= aB; pacc[i][j].x[3] *= aB;
                pacc[i][j].x[4] *= aA; pacc[i][j].x[5] *= aA;
                pacc[i][j].x[6] *= aB; pacc[i][j].x[7] *= aB;
            }
        }
        #pragma unroll
        for (int kk = 0; kk < 4; kk++) {
            wmma::fragment<wmma::matrix_a, 16,16,16, half, wmma::row_major> af[2];
            wmma::fragment<wmma::matrix_b, 16,16,16, half, wmma::row_major> bf[2];
            #pragma unroll
            for (int i = 0; i < 2; i++)
                wmma::load_matrix_sync(af[i], sP + (wr*32 + i*16)*PP + kk*16, PP);
            #pragma unroll
            for (int j = 0; j < 2; j++)
                wmma::load_matrix_sync(bf[j], hV + (kk*16)*HP + wc*32 + j*16, HP);
            #pragma unroll
            for (int i = 0; i < 2; i++)
                #pragma unroll
                for (int j = 0; j < 2; j++)
                    wmma::mma_sync(pacc[i][j], af[i], bf[j], pacc[i][j]);
        }
        __syncthreads();   // E
    }

    #pragma unroll
    for (int rr = 0; rr < 8; rr++)
        if (lane == 0) sL[warp*8 + rr] = l[rr];
    __syncthreads();

    #pragma unroll
    for (int i = 0; i < 2; i++) {
        int rowA = wr*32 + i*16 + (lane >> 2);
        int rowB = rowA + 8;
        float invA = 1.0f / sL[rowA];
        float invB = 1.0f / sL[rowB];
        size_t baseA = ((size_t)((b*LL + q0 + rowA)*NQH + h))*HD;
        size_t baseB = ((size_t)((b*LL + q0 + rowB)*NQH + h))*HD;
        #pragma unroll
        for (int j = 0; j < 2; j++) {
            int c0 = wc*32 + j*16 + 2*(lane & 3);
            *(half2*)(O + baseA + c0)     = __floats2half2_rn(pacc[i][j].x[0]*invA, pacc[i][j].x[1]*invA);
            *(half2*)(O + baseB + c0)     = __floats2half2_rn(pacc[i][j].x[2]*invB, pacc[i][j].x[3]*invB);
            *(half2*)(O + baseA + c0 + 8) = __floats2half2_rn(pacc[i][j].x[4]*invA, pacc[i][j].x[5]*invA);
            *(half2*)(O + baseB + c0 + 8) = __floats2half2_rn(pacc[i][j].x[6]*invB, pacc[i][j].x[7]*invB);
        }
    }
}

// ---------------- silu(g) * u -> fp16 (fp16 in) ----------------
__global__ void silu_mul_kernel(const half* __restrict__ g, const half* __restrict__ u,
                                half* __restrict__ out, int n4)
{
    int i = blockIdx.x * blockDim.x + threadIdx.x;
    if (i >= n4) return;
    HPack gp, up;
    gp.u = ((const uint2*)g)[i];
    up.u = ((const uint2*)u)[i];
    float2 g0 = __half22float2(gp.h[0]), g1 = __half22float2(gp.h[1]);
    float2 u0 = __half22float2(up.h[0]), u1 = __half22float2(up.h[1]);
    ((uint2*)out)[i] = pack4(
        g0.x / (1.f + __expf(-g0.x)) * u0.x,
        g0.y / (1.f + __expf(-g0.y)) * u0.y,
        g1.x / (1.f + __expf(-g1.x)) * u1.x,
        g1.y / (1.f + __expf(-g1.y)) * u1.y);
}

// ---------------- launch ----------------
extern "C" void kernel_launch(void* const* d_in, const int* in_sizes, int n_in,
                              void* d_out, int out_size)
{
    const float* x   = (const float*)d_in[0];
    const float* ln1 = (const float*)d_in[1];
    const float* wq  = (const float*)d_in[2];
    const float* wk  = (const float*)d_in[3];
    const float* wv  = (const float*)d_in[4];
    const float* wo  = (const float*)d_in[5];
    const float* ln2 = (const float*)d_in[6];
    const float* wg  = (const float*)d_in[7];
    const float* wu  = (const float*)d_in[8];
    const float* wd  = (const float*)d_in[9];
    float* out = (float*)d_out;

    half *h, *q, *k, *v, *ctx, *h2, *g, *u, *act;
    float *x1, *rsin, *rcos;
    half *wqh, *wkh, *wvh, *woh, *wgh, *wuh, *wdh;
    cudaGetSymbolAddress((void**)&h,   g_h);
    cudaGetSymbolAddress((void**)&q,   g_q);
    cudaGetSymbolAddress((void**)&k,   g_k);
    cudaGetSymbolAddress((void**)&v,   g_v);
    cudaGetSymbolAddress((void**)&ctx, g_ctx);
    cudaGetSymbolAddress((void**)&x1,  g_x1);
    cudaGetSymbolAddress((void**)&h2,  g_h2);
    cudaGetSymbolAddress((void**)&g,   g_g);
    cudaGetSymbolAddress((void**)&u,   g_u);
    cudaGetSymbolAddress((void**)&act, g_act);
    cudaGetSymbolAddress((void**)&wqh, g_wqh);
    cudaGetSymbolAddress((void**)&wkh, g_wkh);
    cudaGetSymbolAddress((void**)&wvh, g_wvh);
    cudaGetSymbolAddress((void**)&woh, g_woh);
    cudaGetSymbolAddress((void**)&wgh, g_wgh);
    cudaGetSymbolAddress((void**)&wuh, g_wuh);
    cudaGetSymbolAddress((void**)&wdh, g_wdh);
    cudaGetSymbolAddress((void**)&rsin, g_rsin);
    cudaGetSymbolAddress((void**)&rcos, g_rcos);

    cudaFuncSetAttribute(attn_kernel,   cudaFuncAttributeMaxDynamicSharedMemorySize, ATTN_SMEM);
    cudaFuncSetAttribute(qkv_kernel,    cudaFuncAttributeMaxDynamicSharedMemorySize, GEMM_SMEM);
    cudaFuncSetAttribute(gu_kernel,     cudaFuncAttributeMaxDynamicSharedMemorySize, GEMM_SMEM);
    cudaFuncSetAttribute(gemm64_kernel, cudaFuncAttributeMaxDynamicSharedMemorySize, GEMM64_SMEM);

    // 0) fused: rmsnorm1 + weights->fp16 + rope tables
    prelude_kernel<<<PRE_BLOCKS, 256>>>(
        x, ln1, h,
        wq, wk, wv, wo, wg, wu, wd,
        wqh, wkh, wvh, woh, wgh, wuh, wdh, rsin, rcos);
    // 1) fused qkv projections -> fp16 q,k,v (rope in epilogue)
    qkv_kernel<<<dim3(12, ROWS/128), 128, GEMM_SMEM>>>(h, wqh, wkh, wvh, q, k, v, rsin, rcos);
    // 2) attention -> fp16 ctx
    attn_kernel<<<dim3(LL / TQ, NQH, BB), 256, ATTN_SMEM>>>(q, k, v, ctx);
    // 3) output proj + residual -> fp32 x1 (64-row tiles, grid 512)
    gemm64_kernel<<<dim3(DD/128, ROWS/64), 128, GEMM64_SMEM>>>(ctx, woh, x, x1, DD, DD);
    // 4) rmsnorm2 -> fp16
    rmsnorm_kernel<<<ROWS, 256>>>(x1, ln2, h2);
    // 5) fused ffn gate+up -> fp16 g,u
    gu_kernel<<<dim3(64, ROWS/128), 128, GEMM_SMEM>>>(h2, wgh, wuh, g, u);
    // 6) silu*mul -> fp16 act
    {
        int n4 = ROWS * FFND / 4;
        silu_mul_kernel<<<(n4 + 255) / 256, 256>>>(g, u, act, n4);
    }
    // 7) down proj + residual -> out (64-row tiles, grid 512)
    gemm64_kernel<<<dim3(DD/128, ROWS/64), 128, GEMM64_SMEM>>>(act, wdh, x1, out, FFND, DD);
}